// round 6
// baseline (speedup 1.0000x reference)
#include <cuda_runtime.h>
#include <cuda_bf16.h>
#include <cstdint>

// Problem constants (fixed by setup_inputs)
#define BATCH   8
#define S_LEN   1024
#define D_MODEL 1024
#define NH      16
#define DH      64
#define M_ROWS  (BATCH * S_LEN)   // 8192
#define DD      (D_MODEL * D_MODEL)

// ---------------------------------------------------------------------------
// Scratch (device globals — no allocations allowed)
// ---------------------------------------------------------------------------
__device__ float g_Qp[M_ROWS * D_MODEL];
__device__ float g_Kp[M_ROWS * D_MODEL];
__device__ float g_Vp[M_ROWS * D_MODEL];
__device__ float g_Ao[M_ROWS * D_MODEL];
__device__ float g_Wh[4 * DD];   // tf32-hi of Wq,Wk,Wv,Wo
__device__ float g_Wl[4 * DD];   // tf32-lo

// ---------------------------------------------------------------------------
// tf32 helpers (3xTF32: a = ah + al, error-compensated tensor-core fp32)
// ---------------------------------------------------------------------------
__device__ __forceinline__ uint32_t f2tf32(float x) {
    uint32_t r;
    asm("cvt.rna.tf32.f32 %0, %1;" : "=r"(r) : "f"(x));
    return r;
}
__device__ __forceinline__ void split_tf32(float x, uint32_t& h, uint32_t& l) {
    h = f2tf32(x);
    l = f2tf32(x - __uint_as_float(h));
}
__device__ __forceinline__ void split_f(float x, float& h, float& l) {
    uint32_t hh = f2tf32(x);
    h = __uint_as_float(hh);
    l = __uint_as_float(f2tf32(x - h));
}
__device__ __forceinline__ void mma_tf32(float* c, const uint32_t* a, uint32_t b0, uint32_t b1) {
    asm volatile(
        "mma.sync.aligned.m16n8k8.row.col.f32.tf32.tf32.f32 "
        "{%0,%1,%2,%3}, {%4,%5,%6,%7}, {%8,%9}, {%0,%1,%2,%3};\n"
        : "+f"(c[0]), "+f"(c[1]), "+f"(c[2]), "+f"(c[3])
        : "r"(a[0]), "r"(a[1]), "r"(a[2]), "r"(a[3]), "r"(b0), "r"(b1));
}

// ---------------------------------------------------------------------------
// Weight pre-split: W -> (tf32 hi, tf32 lo), once per launch.
// grid: (DD/1024, 4); 256 threads, float4 per thread.
// ---------------------------------------------------------------------------
__global__ void split_weights_kernel(
    const float* __restrict__ W0, const float* __restrict__ W1,
    const float* __restrict__ W2, const float* __restrict__ W3,
    float* __restrict__ H, float* __restrict__ L)
{
    const int z = blockIdx.y;
    const float* W = (z == 0) ? W0 : (z == 1) ? W1 : (z == 2) ? W2 : W3;
    const size_t base = (size_t)z * DD;
    const size_t i = ((size_t)blockIdx.x * 256 + threadIdx.x) * 4;
    float4 x = *(const float4*)(W + i);
    float4 h4, l4;
    split_f(x.x, h4.x, l4.x);
    split_f(x.y, h4.y, l4.y);
    split_f(x.z, h4.z, l4.z);
    split_f(x.w, h4.w, l4.w);
    *(float4*)(H + base + i) = h4;
    *(float4*)(L + base + i) = l4;
}

// ---------------------------------------------------------------------------
// GEMM v2:  C[M,N] = A[M,K] @ W[N,K]^T + bias[N]   (NT, tf32 x3)
// 128x128x16 CTA tile, 512 threads (16 warps, warp tile 32x32).
// A split to hi/lo at smem-store; W pre-split in global.
// Fused over blockIdx.z (selects A / bias / C / weight slab widx0+z).
// Smem stride 20: fragment reads conflict-free (bank = (20*gi+t4)%32 perm).
// ---------------------------------------------------------------------------
#define GBM 128
#define GBN 128
#define GBK 16
#define GLD (GBK + 4)   // 20

__global__ void __launch_bounds__(512, 1) gemm3_tf32(
    const float* __restrict__ A0, const float* __restrict__ A1, const float* __restrict__ A2,
    const float* __restrict__ Wh, const float* __restrict__ Wl,
    const float* __restrict__ b0, const float* __restrict__ b1, const float* __restrict__ b2,
    float* __restrict__ C0, float* __restrict__ C1, float* __restrict__ C2,
    int widx0)
{
    __shared__ float Ash[GBM][GLD];
    __shared__ float Asl[GBM][GLD];
    __shared__ float Bsh[GBN][GLD];
    __shared__ float Bsl[GBN][GLD];

    const int z = blockIdx.z;
    const float* A    = (z == 0) ? A0 : (z == 1) ? A1 : A2;
    const float* bias = (z == 0) ? b0 : (z == 1) ? b1 : b2;
    float*       C    = (z == 0) ? C0 : (z == 1) ? C1 : C2;
    const float* Bh = Wh + (size_t)(widx0 + z) * DD;
    const float* Bl = Wl + (size_t)(widx0 + z) * DD;

    const int tid  = threadIdx.x;
    const int lane = tid & 31;
    const int warp = tid >> 5;
    const int wm = warp & 3;           // m0 = wm*32
    const int wn = warp >> 2;          // n0 = wn*32
    const int gi = lane >> 2;
    const int t4 = lane & 3;

    const int bm = blockIdx.y * GBM;
    const int bn = blockIdx.x * GBN;

    // loader: 512 threads x float4 covers one 128x16 tile per array
    const int lr = tid >> 2;           // 0..127
    const int lc = (tid & 3) * 4;      // 0,4,8,12
    const float* Ag  = A  + (size_t)(bm + lr) * D_MODEL + lc;
    const float* Bhg = Bh + (size_t)(bn + lr) * D_MODEL + lc;
    const float* Blg = Bl + (size_t)(bn + lr) * D_MODEL + lc;

    float acc[2][4][4];
    #pragma unroll
    for (int mt = 0; mt < 2; mt++)
        #pragma unroll
        for (int nt = 0; nt < 4; nt++)
            #pragma unroll
            for (int i = 0; i < 4; i++) acc[mt][nt][i] = 0.0f;

    float4 pa  = *(const float4*)(Ag);
    float4 pbh = *(const float4*)(Bhg);
    float4 pbl = *(const float4*)(Blg);

    for (int k0 = 0; k0 < D_MODEL; k0 += GBK) {
        __syncthreads();
        {
            float4 ah4, al4;
            split_f(pa.x, ah4.x, al4.x);
            split_f(pa.y, ah4.y, al4.y);
            split_f(pa.z, ah4.z, al4.z);
            split_f(pa.w, ah4.w, al4.w);
            *(float4*)&Ash[lr][lc] = ah4;
            *(float4*)&Asl[lr][lc] = al4;
            *(float4*)&Bsh[lr][lc] = pbh;
            *(float4*)&Bsl[lr][lc] = pbl;
        }
        __syncthreads();

        if (k0 + GBK < D_MODEL) {
            pa  = *(const float4*)(Ag  + k0 + GBK);
            pbh = *(const float4*)(Bhg + k0 + GBK);
            pbl = *(const float4*)(Blg + k0 + GBK);
        }

        #pragma unroll
        for (int kk = 0; kk < GBK; kk += 8) {
            uint32_t ah[2][4], al[2][4];
            #pragma unroll
            for (int mt = 0; mt < 2; mt++) {
                const int r = wm * 32 + mt * 16 + gi;
                ah[mt][0] = __float_as_uint(Ash[r][kk + t4]);
                al[mt][0] = __float_as_uint(Asl[r][kk + t4]);
                ah[mt][1] = __float_as_uint(Ash[r + 8][kk + t4]);
                al[mt][1] = __float_as_uint(Asl[r + 8][kk + t4]);
                ah[mt][2] = __float_as_uint(Ash[r][kk + t4 + 4]);
                al[mt][2] = __float_as_uint(Asl[r][kk + t4 + 4]);
                ah[mt][3] = __float_as_uint(Ash[r + 8][kk + t4 + 4]);
                al[mt][3] = __float_as_uint(Asl[r + 8][kk + t4 + 4]);
            }
            uint32_t bh[4][2], bl[4][2];
            #pragma unroll
            for (int nt = 0; nt < 4; nt++) {
                const int rb = wn * 32 + nt * 8 + gi;
                bh[nt][0] = __float_as_uint(Bsh[rb][kk + t4]);
                bl[nt][0] = __float_as_uint(Bsl[rb][kk + t4]);
                bh[nt][1] = __float_as_uint(Bsh[rb][kk + t4 + 4]);
                bl[nt][1] = __float_as_uint(Bsl[rb][kk + t4 + 4]);
            }
            #pragma unroll
            for (int mt = 0; mt < 2; mt++)
                #pragma unroll
                for (int nt = 0; nt < 4; nt++) {
                    mma_tf32(acc[mt][nt], al[mt], bh[nt][0], bh[nt][1]);
                    mma_tf32(acc[mt][nt], ah[mt], bl[nt][0], bl[nt][1]);
                    mma_tf32(acc[mt][nt], ah[mt], bh[nt][0], bh[nt][1]);
                }
        }
    }

    #pragma unroll
    for (int nt = 0; nt < 4; nt++) {
        const int col = bn + wn * 32 + nt * 8 + 2 * t4;
        const float2 bb = *(const float2*)(bias + col);
        #pragma unroll
        for (int mt = 0; mt < 2; mt++) {
            const int row0 = bm + wm * 32 + mt * 16 + gi;
            float2 o0, o1;
            o0.x = acc[mt][nt][0] + bb.x; o0.y = acc[mt][nt][1] + bb.y;
            o1.x = acc[mt][nt][2] + bb.x; o1.y = acc[mt][nt][3] + bb.y;
            *(float2*)(C + (size_t)row0 * D_MODEL + col)       = o0;
            *(float2*)(C + (size_t)(row0 + 8) * D_MODEL + col) = o1;
        }
    }
}

// ---------------------------------------------------------------------------
// Tensor-core flash attention (tf32 x3), causal + key padding mask.
// Grid (S/128, H, B), 256 threads = 8 warps; warp w owns 16 query rows.
// K and V tiles pre-split to tf32 hi/lo at tile load (split once, read many).
//  - K tiles: LDK=64, XOR swizzle col^=((row&7)<<2) -> conflict-free b-frags.
//  - V tiles: LDV=72 -> conflict-free column-fragment reads.
//  - P round-trips through per-warp smem (LDP=68), split on read.
// ---------------------------------------------------------------------------
#define AT_LDK 64
#define AT_LDV 72
#define AT_LDP 68
#define AT_SMEM ((2*64*AT_LDK + 2*64*AT_LDV + 8*16*AT_LDP + 64) * 4)

__global__ void __launch_bounds__(256, 1) attn_mma_kernel(
    const float* __restrict__ Q, const float* __restrict__ K,
    const float* __restrict__ V, const unsigned char* __restrict__ kpm,
    float* __restrict__ O)
{
    extern __shared__ float sm[];
    float* Ksh  = sm;                          // 64 x 64 (swizzled), hi
    float* Ksl  = Ksh + 64 * AT_LDK;           // lo
    float* Vsh  = Ksl + 64 * AT_LDK;           // 64 x 72, hi
    float* Vsl  = Vsh + 64 * AT_LDV;           // lo
    float* Ps   = Vsl + 64 * AT_LDV;           // 8 warps x 16 x 68
    float* mneg = Ps + 8 * 16 * AT_LDP;        // 64

    const int b   = blockIdx.z;
    const int h   = blockIdx.y;
    const int qt  = gridDim.x - 1 - blockIdx.x;   // heavy tiles first
    const int tid = threadIdx.x;
    const int w    = tid >> 5;
    const int lane = tid & 31;
    const int gi = lane >> 2;
    const int t4 = lane & 3;

    const int q0   = qt * 128;
    const int row0 = q0 + w * 16 + gi;        // rows: row0, row0+8

    const float scale = 0.125f;               // 1/sqrt(64)
    const float NEG = -1e30f;
    const size_t rstride = (size_t)NH * DH;

    // ---- Q fragments, register-resident, pre-split hi/lo ----
    uint32_t qh[8][4], ql[8][4];
    {
        const float* qp0 = Q + ((size_t)(b * S_LEN + row0) * NH + h) * DH;
        const float* qp1 = qp0 + 8 * rstride;
        #pragma unroll
        for (int kc = 0; kc < 8; kc++) {
            split_tf32(qp0[kc * 8 + t4],     qh[kc][0], ql[kc][0]);
            split_tf32(qp1[kc * 8 + t4],     qh[kc][1], ql[kc][1]);
            split_tf32(qp0[kc * 8 + t4 + 4], qh[kc][2], ql[kc][2]);
            split_tf32(qp1[kc * 8 + t4 + 4], qh[kc][3], ql[kc][3]);
        }
    }

    float oc[8][4];
    #pragma unroll
    for (int nt = 0; nt < 8; nt++)
        #pragma unroll
        for (int i = 0; i < 4; i++) oc[nt][i] = 0.0f;
    float m0 = NEG, m1 = NEG, l0 = 0.0f, l1 = 0.0f;

    // tile loader mapping
    const int lr = tid >> 2;                 // key row 0..63
    const int lc = (tid & 3) * 16;           // dim segment
    const int swz = (lr & 7) << 2;

    float* pw = Ps + w * 16 * AT_LDP;
    const int ktiles = 2 * qt + 2;

    for (int kt = 0; kt < ktiles; kt++) {
        const int k0 = kt * 64;
        __syncthreads();
        {
            const float* krow = K + ((size_t)(b * S_LEN + k0 + lr) * NH + h) * DH + lc;
            const float* vrow = V + ((size_t)(b * S_LEN + k0 + lr) * NH + h) * DH + lc;
            #pragma unroll
            for (int c = 0; c < 4; c++) {
                float4 kv = *(const float4*)(krow + 4 * c);
                float4 vv = *(const float4*)(vrow + 4 * c);
                float4 h4, l4;
                split_f(kv.x, h4.x, l4.x);
                split_f(kv.y, h4.y, l4.y);
                split_f(kv.z, h4.z, l4.z);
                split_f(kv.w, h4.w, l4.w);
                const int ko = lr * AT_LDK + ((lc + 4 * c) ^ swz);
                *(float4*)&Ksh[ko] = h4;
                *(float4*)&Ksl[ko] = l4;
                split_f(vv.x, h4.x, l4.x);
                split_f(vv.y, h4.y, l4.y);
                split_f(vv.z, h4.z, l4.z);
                split_f(vv.w, h4.w, l4.w);
                const int vo = lr * AT_LDV + lc + 4 * c;
                *(float4*)&Vsh[vo] = h4;
                *(float4*)&Vsl[vo] = l4;
            }
            if (tid < 64) mneg[tid] = kpm[b * S_LEN + k0 + tid] ? NEG : 0.0f;
        }
        __syncthreads();

        // ---- S = Q K^T (3xTF32) ----
        float sc[8][4];
        #pragma unroll
        for (int nt = 0; nt < 8; nt++)
            #pragma unroll
            for (int i = 0; i < 4; i++) sc[nt][i] = 0.0f;

        #pragma unroll
        for (int kc = 0; kc < 8; kc++) {
            uint32_t bh[8][2], bl[8][2];
            #pragma unroll
            for (int nt = 0; nt < 8; nt++) {
                const int krow = nt * 8 + gi;
                const int ks = (krow & 7) << 2;
                const int o0 = krow * AT_LDK + ((kc * 8 + t4) ^ ks);
                const int o1 = krow * AT_LDK + ((kc * 8 + t4 + 4) ^ ks);
                bh[nt][0] = __float_as_uint(Ksh[o0]);
                bl[nt][0] = __float_as_uint(Ksl[o0]);
                bh[nt][1] = __float_as_uint(Ksh[o1]);
                bl[nt][1] = __float_as_uint(Ksl[o1]);
            }
            #pragma unroll
            for (int nt = 0; nt < 8; nt++) mma_tf32(sc[nt], ql[kc], bh[nt][0], bh[nt][1]);
            #pragma unroll
            for (int nt = 0; nt < 8; nt++) mma_tf32(sc[nt], qh[kc], bl[nt][0], bl[nt][1]);
            #pragma unroll
            for (int nt = 0; nt < 8; nt++) mma_tf32(sc[nt], qh[kc], bh[nt][0], bh[nt][1]);
        }

        // ---- scale + masks + online softmax ----
        const bool needc = (k0 + 63) > row0;
        float rm0 = NEG, rm1 = NEG;
        #pragma unroll
        for (int nt = 0; nt < 8; nt++) {
            const int col = k0 + nt * 8 + 2 * t4;
            const float mg0 = mneg[nt * 8 + 2 * t4];
            const float mg1 = mneg[nt * 8 + 2 * t4 + 1];
            float v0 = sc[nt][0] * scale + mg0;
            float v1 = sc[nt][1] * scale + mg1;
            float v2 = sc[nt][2] * scale + mg0;
            float v3 = sc[nt][3] * scale + mg1;
            if (needc) {
                if (col     > row0)     v0 = NEG;
                if (col + 1 > row0)     v1 = NEG;
                if (col     > row0 + 8) v2 = NEG;
                if (col + 1 > row0 + 8) v3 = NEG;
            }
            sc[nt][0] = v0; sc[nt][1] = v1; sc[nt][2] = v2; sc[nt][3] = v3;
            rm0 = fmaxf(rm0, fmaxf(v0, v1));
            rm1 = fmaxf(rm1, fmaxf(v2, v3));
        }
        rm0 = fmaxf(rm0, __shfl_xor_sync(0xffffffffu, rm0, 1, 4));
        rm0 = fmaxf(rm0, __shfl_xor_sync(0xffffffffu, rm0, 2, 4));
        rm1 = fmaxf(rm1, __shfl_xor_sync(0xffffffffu, rm1, 1, 4));
        rm1 = fmaxf(rm1, __shfl_xor_sync(0xffffffffu, rm1, 2, 4));

        const float mn0 = fmaxf(m0, rm0);
        const float mn1 = fmaxf(m1, rm1);
        const float cr0 = __expf(m0 - mn0);
        const float cr1 = __expf(m1 - mn1);

        float ps0 = 0.0f, ps1 = 0.0f;
        #pragma unroll
        for (int nt = 0; nt < 8; nt++) {
            const float e0 = __expf(sc[nt][0] - mn0);
            const float e1 = __expf(sc[nt][1] - mn0);
            const float e2 = __expf(sc[nt][2] - mn1);
            const float e3 = __expf(sc[nt][3] - mn1);
            sc[nt][0] = e0; sc[nt][1] = e1; sc[nt][2] = e2; sc[nt][3] = e3;
            ps0 += e0 + e1;
            ps1 += e2 + e3;
        }
        ps0 += __shfl_xor_sync(0xffffffffu, ps0, 1, 4);
        ps0 += __shfl_xor_sync(0xffffffffu, ps0, 2, 4);
        ps1 += __shfl_xor_sync(0xffffffffu, ps1, 1, 4);
        ps1 += __shfl_xor_sync(0xffffffffu, ps1, 2, 4);

        l0 = l0 * cr0 + ps0;  m0 = mn0;
        l1 = l1 * cr1 + ps1;  m1 = mn1;

        #pragma unroll
        for (int nt = 0; nt < 8; nt++) {
            oc[nt][0] *= cr0; oc[nt][1] *= cr0;
            oc[nt][2] *= cr1; oc[nt][3] *= cr1;
        }

        // ---- P -> per-warp smem (A-operand layout fixup) ----
        __syncwarp();
        #pragma unroll
        for (int nt = 0; nt < 8; nt++) {
            float2 p01; p01.x = sc[nt][0]; p01.y = sc[nt][1];
            float2 p23; p23.x = sc[nt][2]; p23.y = sc[nt][3];
            *(float2*)&pw[gi * AT_LDP + nt * 8 + 2 * t4]       = p01;
            *(float2*)&pw[(gi + 8) * AT_LDP + nt * 8 + 2 * t4] = p23;
        }
        __syncwarp();

        // ---- O += P V (3xTF32) ----
        #pragma unroll
        for (int kc = 0; kc < 8; kc++) {
            uint32_t ah[4], al[4];
            split_tf32(pw[gi * AT_LDP + kc * 8 + t4],           ah[0], al[0]);
            split_tf32(pw[(gi + 8) * AT_LDP + kc * 8 + t4],     ah[1], al[1]);
            split_tf32(pw[gi * AT_LDP + kc * 8 + t4 + 4],       ah[2], al[2]);
            split_tf32(pw[(gi + 8) * AT_LDP + kc * 8 + t4 + 4], ah[3], al[3]);

            uint32_t bh[8][2], bl[8][2];
            #pragma unroll
            for (int nt = 0; nt < 8; nt++) {
                const int o0 = (kc * 8 + t4) * AT_LDV + nt * 8 + gi;
                const int o1 = (kc * 8 + t4 + 4) * AT_LDV + nt * 8 + gi;
                bh[nt][0] = __float_as_uint(Vsh[o0]);
                bl[nt][0] = __float_as_uint(Vsl[o0]);
                bh[nt][1] = __float_as_uint(Vsh[o1]);
                bl[nt][1] = __float_as_uint(Vsl[o1]);
            }
            #pragma unroll
            for (int nt = 0; nt < 8; nt++) mma_tf32(oc[nt], al, bh[nt][0], bh[nt][1]);
            #pragma unroll
            for (int nt = 0; nt < 8; nt++) mma_tf32(oc[nt], ah, bl[nt][0], bl[nt][1]);
            #pragma unroll
            for (int nt = 0; nt < 8; nt++) mma_tf32(oc[nt], ah, bh[nt][0], bh[nt][1]);
        }
    }

    // ---- normalize + store ----
    const float inv0 = 1.0f / l0;
    const float inv1 = 1.0f / l1;
    float* op0 = O + ((size_t)(b * S_LEN + row0) * NH + h) * DH;
    float* op1 = op0 + 8 * rstride;
    #pragma unroll
    for (int nt = 0; nt < 8; nt++) {
        float2 w0, w1;
        w0.x = oc[nt][0] * inv0; w0.y = oc[nt][1] * inv0;
        w1.x = oc[nt][2] * inv1; w1.y = oc[nt][3] * inv1;
        *(float2*)(op0 + nt * 8 + 2 * t4) = w0;
        *(float2*)(op1 + nt * 8 + 2 * t4) = w1;
    }
}

// ---------------------------------------------------------------------------
// Launch
// ---------------------------------------------------------------------------
extern "C" void kernel_launch(void* const* d_in, const int* in_sizes, int n_in,
                              void* d_out, int out_size)
{
    const float* q    = (const float*)d_in[0];
    const float* k    = (const float*)d_in[1];
    const float* v    = (const float*)d_in[2];
    const unsigned char* kpm = (const unsigned char*)d_in[3];
    const float* Wq = (const float*)d_in[4];
    const float* bq = (const float*)d_in[5];
    const float* Wk = (const float*)d_in[6];
    const float* bk = (const float*)d_in[7];
    const float* Wv = (const float*)d_in[8];
    const float* bv = (const float*)d_in[9];
    const float* Wo = (const float*)d_in[10];
    const float* bo = (const float*)d_in[11];
    float* out = (float*)d_out;

    void *pQp, *pKp, *pVp, *pAo, *pWh, *pWl;
    cudaGetSymbolAddress(&pQp, g_Qp);
    cudaGetSymbolAddress(&pKp, g_Kp);
    cudaGetSymbolAddress(&pVp, g_Vp);
    cudaGetSymbolAddress(&pAo, g_Ao);
    cudaGetSymbolAddress(&pWh, g_Wh);
    cudaGetSymbolAddress(&pWl, g_Wl);

    cudaFuncSetAttribute(attn_mma_kernel,
                         cudaFuncAttributeMaxDynamicSharedMemorySize, AT_SMEM);

    // 1) pre-split weights (Wq,Wk,Wv,Wo) -> tf32 hi/lo slabs
    dim3 sgrid(DD / 1024, 4);
    split_weights_kernel<<<sgrid, 256>>>(Wq, Wk, Wv, Wo, (float*)pWh, (float*)pWl);

    // 2) fused Q/K/V projections
    dim3 ggrid(D_MODEL / GBN, M_ROWS / GBM, 3);   // (8, 64, 3)
    gemm3_tf32<<<ggrid, 512>>>(q, k, v, (const float*)pWh, (const float*)pWl,
                               bq, bk, bv,
                               (float*)pQp, (float*)pKp, (float*)pVp, 0);

    // 3) attention
    dim3 agrid(S_LEN / 128, NH, BATCH);            // (8, 16, 8)
    attn_mma_kernel<<<agrid, 256, AT_SMEM>>>((const float*)pQp, (const float*)pKp,
                                             (const float*)pVp, kpm, (float*)pAo);

    // 4) output projection (weight slab 3)
    dim3 ogrid(D_MODEL / GBN, M_ROWS / GBM, 1);
    gemm3_tf32<<<ogrid, 512>>>((const float*)pAo, (const float*)pAo, (const float*)pAo,
                               (const float*)pWh, (const float*)pWl,
                               bo, bo, bo,
                               out, out, out, 3);
}

// round 7
// speedup vs baseline: 1.4681x; 1.4681x over previous
#include <cuda_runtime.h>
#include <cuda_bf16.h>
#include <cstdint>

// Problem constants (fixed by setup_inputs)
#define BATCH   8
#define S_LEN   1024
#define D_MODEL 1024
#define NH      16
#define DH      64
#define M_ROWS  (BATCH * S_LEN)   // 8192
#define DD      (D_MODEL * D_MODEL)
#define DU      (D_MODEL / 2)     // u32 (bf16x2) per row

// ---------------------------------------------------------------------------
// Scratch (device globals — no allocations allowed)
// ---------------------------------------------------------------------------
__device__ float    g_Qp[M_ROWS * D_MODEL];
__device__ float    g_Kp[M_ROWS * D_MODEL];
__device__ float    g_Vp[M_ROWS * D_MODEL];
__device__ float    g_Ao[M_ROWS * D_MODEL];
__device__ uint32_t g_Whp[4 * DD / 2];   // packed bf16x2 hi of Wq,Wk,Wv,Wo
__device__ uint32_t g_Wlp[4 * DD / 2];   // packed bf16x2 lo

// ---------------------------------------------------------------------------
// bf16 helpers (3xBF16: x = h + l; keep ah*bh + ah*bl + al*bh)
// ---------------------------------------------------------------------------
__device__ __forceinline__ uint32_t bpack(float x0, float x1) {
    __nv_bfloat162 t = __floats2bfloat162_rn(x0, x1);   // x0 -> low half
    return *reinterpret_cast<uint32_t*>(&t);
}
__device__ __forceinline__ void bsplit2(float x0, float x1, uint32_t& ph, uint32_t& pl) {
    const float h0 = __bfloat162float(__float2bfloat16(x0));
    const float h1 = __bfloat162float(__float2bfloat16(x1));
    ph = bpack(h0, h1);
    pl = bpack(x0 - h0, x1 - h1);
}
__device__ __forceinline__ void mma_bf16(float* c, const uint32_t* a, uint32_t b0, uint32_t b1) {
    asm volatile(
        "mma.sync.aligned.m16n8k16.row.col.f32.bf16.bf16.f32 "
        "{%0,%1,%2,%3}, {%4,%5,%6,%7}, {%8,%9}, {%0,%1,%2,%3};\n"
        : "+f"(c[0]), "+f"(c[1]), "+f"(c[2]), "+f"(c[3])
        : "r"(a[0]), "r"(a[1]), "r"(a[2]), "r"(a[3]), "r"(b0), "r"(b1));
}

// ---------------------------------------------------------------------------
// tf32 helpers (attention kernel — unchanged, measured-good)
// ---------------------------------------------------------------------------
__device__ __forceinline__ uint32_t f2tf32(float x) {
    uint32_t r;
    asm("cvt.rna.tf32.f32 %0, %1;" : "=r"(r) : "f"(x));
    return r;
}
__device__ __forceinline__ void split_tf32(float x, uint32_t& h, uint32_t& l) {
    h = f2tf32(x);
    l = f2tf32(x - __uint_as_float(h));
}
__device__ __forceinline__ void mma_tf32(float* c, const uint32_t* a, uint32_t b0, uint32_t b1) {
    asm volatile(
        "mma.sync.aligned.m16n8k8.row.col.f32.tf32.tf32.f32 "
        "{%0,%1,%2,%3}, {%4,%5,%6,%7}, {%8,%9}, {%0,%1,%2,%3};\n"
        : "+f"(c[0]), "+f"(c[1]), "+f"(c[2]), "+f"(c[3])
        : "r"(a[0]), "r"(a[1]), "r"(a[2]), "r"(a[3]), "r"(b0), "r"(b1));
}

// ---------------------------------------------------------------------------
// Weight pre-split: W(fp32) -> packed bf16x2 hi/lo slabs, once per launch.
// grid (DD/1024, 4), 256 threads; 4 floats -> 2 u32 per slab per thread.
// ---------------------------------------------------------------------------
__global__ void split_weights_kernel(
    const float* __restrict__ W0, const float* __restrict__ W1,
    const float* __restrict__ W2, const float* __restrict__ W3,
    uint32_t* __restrict__ Hp, uint32_t* __restrict__ Lp)
{
    const int z = blockIdx.y;
    const float* W = (z == 0) ? W0 : (z == 1) ? W1 : (z == 2) ? W2 : W3;
    const size_t fi = ((size_t)blockIdx.x * 256 + threadIdx.x) * 4;
    const size_t ui = (size_t)z * (DD / 2) + fi / 2;
    float4 x = *(const float4*)(W + fi);
    uint2 h2, l2;
    bsplit2(x.x, x.y, h2.x, l2.x);
    bsplit2(x.z, x.w, h2.y, l2.y);
    *(uint2*)(Hp + ui) = h2;
    *(uint2*)(Lp + ui) = l2;
}

// ---------------------------------------------------------------------------
// GEMM v3:  C[M,N] = A[M,K] @ W[N,K]^T + bias[N]   (NT, bf16 x3 tensor-core)
// 128x128x32 CTA tile, 256 threads (8 warps, warp tile 32x64).
// A split+packed to bf16x2 at smem store; W pre-split/packed in global.
// Smem in u32 units, stride 20: fragment reads conflict-free
// (banks (20*gi + t4) % 32 form a permutation over gi=0..7).
// Fused over blockIdx.z (selects A / bias / C / weight slab widx0+z).
// ---------------------------------------------------------------------------
#define GBK 32           // bf16 elements per k-tile
#define GKU (GBK / 2)    // 16 u32 per row
#define GLD (GKU + 4)    // 20

__global__ void __launch_bounds__(256) gemm3_bf16(
    const float* __restrict__ A0, const float* __restrict__ A1, const float* __restrict__ A2,
    const uint32_t* __restrict__ Whp, const uint32_t* __restrict__ Wlp,
    const float* __restrict__ b0, const float* __restrict__ b1, const float* __restrict__ b2,
    float* __restrict__ C0, float* __restrict__ C1, float* __restrict__ C2,
    int widx0)
{
    __shared__ uint32_t Ash[128][GLD];
    __shared__ uint32_t Asl[128][GLD];
    __shared__ uint32_t Bsh[128][GLD];
    __shared__ uint32_t Bsl[128][GLD];

    const int z = blockIdx.z;
    const float* A    = (z == 0) ? A0 : (z == 1) ? A1 : A2;
    const float* bias = (z == 0) ? b0 : (z == 1) ? b1 : b2;
    float*       C    = (z == 0) ? C0 : (z == 1) ? C1 : C2;
    const uint32_t* Bh = Whp + (size_t)(widx0 + z) * (DD / 2);
    const uint32_t* Bl = Wlp + (size_t)(widx0 + z) * (DD / 2);

    const int tid  = threadIdx.x;
    const int lane = tid & 31;
    const int warp = tid >> 5;
    const int wm = warp & 3;           // m0 = wm*32
    const int wn = warp >> 2;          // n0 = wn*64
    const int gi = lane >> 2;
    const int t4 = lane & 3;

    const int bm = blockIdx.y * 128;
    const int bn = blockIdx.x * 128;

    // loader: row = tid/2; A: 16 floats at fc; W: 8 u32 at uc
    const int lr = tid >> 1;
    const int fc = (tid & 1) * 16;
    const int uc = (tid & 1) * 8;
    const float*    Ag  = A  + (size_t)(bm + lr) * D_MODEL + fc;
    const uint32_t* Bhg = Bh + (size_t)(bn + lr) * DU + uc;
    const uint32_t* Blg = Bl + (size_t)(bn + lr) * DU + uc;

    float acc[2][8][4];
    #pragma unroll
    for (int mt = 0; mt < 2; mt++)
        #pragma unroll
        for (int nt = 0; nt < 8; nt++)
            #pragma unroll
            for (int i = 0; i < 4; i++) acc[mt][nt][i] = 0.0f;

    float4 pa[4];
    uint4 pbh[2], pbl[2];
    #pragma unroll
    for (int c = 0; c < 4; c++) pa[c] = *(const float4*)(Ag + 4 * c);
    pbh[0] = *(const uint4*)(Bhg);     pbh[1] = *(const uint4*)(Bhg + 4);
    pbl[0] = *(const uint4*)(Blg);     pbl[1] = *(const uint4*)(Blg + 4);

    for (int k0 = 0; k0 < D_MODEL; k0 += GBK) {
        __syncthreads();
        #pragma unroll
        for (int c = 0; c < 4; c++) {
            uint32_t h01, l01, h23, l23;
            bsplit2(pa[c].x, pa[c].y, h01, l01);
            bsplit2(pa[c].z, pa[c].w, h23, l23);
            Ash[lr][uc + 2 * c]     = h01;
            Ash[lr][uc + 2 * c + 1] = h23;
            Asl[lr][uc + 2 * c]     = l01;
            Asl[lr][uc + 2 * c + 1] = l23;
        }
        *(uint4*)&Bsh[lr][uc]     = pbh[0];
        *(uint4*)&Bsh[lr][uc + 4] = pbh[1];
        *(uint4*)&Bsl[lr][uc]     = pbl[0];
        *(uint4*)&Bsl[lr][uc + 4] = pbl[1];
        __syncthreads();

        if (k0 + GBK < D_MODEL) {
            const int ku = (k0 + GBK) / 2;
            #pragma unroll
            for (int c = 0; c < 4; c++) pa[c] = *(const float4*)(Ag + k0 + GBK + 4 * c);
            pbh[0] = *(const uint4*)(Bhg + ku);     pbh[1] = *(const uint4*)(Bhg + ku + 4);
            pbl[0] = *(const uint4*)(Blg + ku);     pbl[1] = *(const uint4*)(Blg + ku + 4);
        }

        #pragma unroll
        for (int kk = 0; kk < GKU; kk += 8) {    // two k16 steps
            uint32_t ah[2][4], al[2][4];
            #pragma unroll
            for (int mt = 0; mt < 2; mt++) {
                const int r = wm * 32 + mt * 16 + gi;
                ah[mt][0] = Ash[r][kk + t4];
                al[mt][0] = Asl[r][kk + t4];
                ah[mt][1] = Ash[r + 8][kk + t4];
                al[mt][1] = Asl[r + 8][kk + t4];
                ah[mt][2] = Ash[r][kk + t4 + 4];
                al[mt][2] = Asl[r][kk + t4 + 4];
                ah[mt][3] = Ash[r + 8][kk + t4 + 4];
                al[mt][3] = Asl[r + 8][kk + t4 + 4];
            }
            #pragma unroll
            for (int nt = 0; nt < 8; nt++) {
                const int rb = wn * 64 + nt * 8 + gi;
                const uint32_t bh0 = Bsh[rb][kk + t4];
                const uint32_t bh1 = Bsh[rb][kk + t4 + 4];
                const uint32_t bl0 = Bsl[rb][kk + t4];
                const uint32_t bl1 = Bsl[rb][kk + t4 + 4];
                #pragma unroll
                for (int mt = 0; mt < 2; mt++) {
                    mma_bf16(acc[mt][nt], al[mt], bh0, bh1);
                    mma_bf16(acc[mt][nt], ah[mt], bl0, bl1);
                    mma_bf16(acc[mt][nt], ah[mt], bh0, bh1);
                }
            }
        }
    }

    #pragma unroll
    for (int nt = 0; nt < 8; nt++) {
        const int col = bn + wn * 64 + nt * 8 + 2 * t4;
        const float2 bb = *(const float2*)(bias + col);
        #pragma unroll
        for (int mt = 0; mt < 2; mt++) {
            const int row0 = bm + wm * 32 + mt * 16 + gi;
            float2 o0, o1;
            o0.x = acc[mt][nt][0] + bb.x; o0.y = acc[mt][nt][1] + bb.y;
            o1.x = acc[mt][nt][2] + bb.x; o1.y = acc[mt][nt][3] + bb.y;
            *(float2*)(C + (size_t)row0 * D_MODEL + col)       = o0;
            *(float2*)(C + (size_t)(row0 + 8) * D_MODEL + col) = o1;
        }
    }
}

// ---------------------------------------------------------------------------
// Tensor-core flash attention (tf32 x3) — EXACT round-5 version (563.5 us).
// ---------------------------------------------------------------------------
#define AT_LDK 64
#define AT_LDV 72
#define AT_LDP 68
#define AT_SMEM ((64*AT_LDK + 64*AT_LDV + 8*16*AT_LDP + 64) * 4)

__global__ void __launch_bounds__(256, 1) attn_mma_kernel(
    const float* __restrict__ Q, const float* __restrict__ K,
    const float* __restrict__ V, const unsigned char* __restrict__ kpm,
    float* __restrict__ O)
{
    extern __shared__ float sm[];
    float* Ks   = sm;                          // 64 x 64 (swizzled)
    float* Vs   = Ks + 64 * AT_LDK;            // 64 x 72
    float* Ps   = Vs + 64 * AT_LDV;            // 8 warps x 16 x 68
    float* mneg = Ps + 8 * 16 * AT_LDP;        // 64

    const int b   = blockIdx.z;
    const int h   = blockIdx.y;
    const int qt  = gridDim.x - 1 - blockIdx.x;   // heavy tiles first
    const int tid = threadIdx.x;
    const int w    = tid >> 5;
    const int lane = tid & 31;
    const int gi = lane >> 2;
    const int t4 = lane & 3;

    const int q0   = qt * 128;
    const int row0 = q0 + w * 16 + gi;        // rows: row0, row0+8

    const float scale = 0.125f;               // 1/sqrt(64)
    const float NEG = -1e30f;
    const size_t rstride = (size_t)NH * DH;

    uint32_t qh[8][4], ql[8][4];
    {
        const float* qp0 = Q + ((size_t)(b * S_LEN + row0) * NH + h) * DH;
        const float* qp1 = qp0 + 8 * rstride;
        #pragma unroll
        for (int kc = 0; kc < 8; kc++) {
            split_tf32(qp0[kc * 8 + t4],     qh[kc][0], ql[kc][0]);
            split_tf32(qp1[kc * 8 + t4],     qh[kc][1], ql[kc][1]);
            split_tf32(qp0[kc * 8 + t4 + 4], qh[kc][2], ql[kc][2]);
            split_tf32(qp1[kc * 8 + t4 + 4], qh[kc][3], ql[kc][3]);
        }
    }

    float oc[8][4];
    #pragma unroll
    for (int nt = 0; nt < 8; nt++)
        #pragma unroll
        for (int i = 0; i < 4; i++) oc[nt][i] = 0.0f;
    float m0 = NEG, m1 = NEG, l0 = 0.0f, l1 = 0.0f;

    const int lr = tid >> 2;
    const int lc = (tid & 3) * 16;
    const int swz = (lr & 7) << 2;

    float* pw = Ps + w * 16 * AT_LDP;
    const int ktiles = 2 * qt + 2;

    for (int kt = 0; kt < ktiles; kt++) {
        const int k0 = kt * 64;
        __syncthreads();
        {
            const float* krow = K + ((size_t)(b * S_LEN + k0 + lr) * NH + h) * DH + lc;
            const float* vrow = V + ((size_t)(b * S_LEN + k0 + lr) * NH + h) * DH + lc;
            #pragma unroll
            for (int c = 0; c < 4; c++) {
                *(float4*)&Ks[lr * AT_LDK + ((lc + 4 * c) ^ swz)] = *(const float4*)(krow + 4 * c);
                *(float4*)&Vs[lr * AT_LDV + lc + 4 * c]           = *(const float4*)(vrow + 4 * c);
            }
            if (tid < 64) mneg[tid] = kpm[b * S_LEN + k0 + tid] ? NEG : 0.0f;
        }
        __syncthreads();

        float sc[8][4];
        #pragma unroll
        for (int nt = 0; nt < 8; nt++)
            #pragma unroll
            for (int i = 0; i < 4; i++) sc[nt][i] = 0.0f;

        #pragma unroll
        for (int kc = 0; kc < 8; kc++) {
            uint32_t bh[8][2], bl[8][2];
            #pragma unroll
            for (int nt = 0; nt < 8; nt++) {
                const int krw = nt * 8 + gi;
                const int ks = (krw & 7) << 2;
                split_tf32(Ks[krw * AT_LDK + ((kc * 8 + t4) ^ ks)],     bh[nt][0], bl[nt][0]);
                split_tf32(Ks[krw * AT_LDK + ((kc * 8 + t4 + 4) ^ ks)], bh[nt][1], bl[nt][1]);
            }
            #pragma unroll
            for (int nt = 0; nt < 8; nt++) mma_tf32(sc[nt], ql[kc], bh[nt][0], bh[nt][1]);
            #pragma unroll
            for (int nt = 0; nt < 8; nt++) mma_tf32(sc[nt], qh[kc], bl[nt][0], bl[nt][1]);
            #pragma unroll
            for (int nt = 0; nt < 8; nt++) mma_tf32(sc[nt], qh[kc], bh[nt][0], bh[nt][1]);
        }

        const bool needc = (k0 + 63) > row0;
        float rm0 = NEG, rm1 = NEG;
        #pragma unroll
        for (int nt = 0; nt < 8; nt++) {
            const int col = k0 + nt * 8 + 2 * t4;
            const float mg0 = mneg[nt * 8 + 2 * t4];
            const float mg1 = mneg[nt * 8 + 2 * t4 + 1];
            float v0 = sc[nt][0] * scale + mg0;
            float v1 = sc[nt][1] * scale + mg1;
            float v2 = sc[nt][2] * scale + mg0;
            float v3 = sc[nt][3] * scale + mg1;
            if (needc) {
                if (col     > row0)     v0 = NEG;
                if (col + 1 > row0)     v1 = NEG;
                if (col     > row0 + 8) v2 = NEG;
                if (col + 1 > row0 + 8) v3 = NEG;
            }
            sc[nt][0] = v0; sc[nt][1] = v1; sc[nt][2] = v2; sc[nt][3] = v3;
            rm0 = fmaxf(rm0, fmaxf(v0, v1));
            rm1 = fmaxf(rm1, fmaxf(v2, v3));
        }
        rm0 = fmaxf(rm0, __shfl_xor_sync(0xffffffffu, rm0, 1, 4));
        rm0 = fmaxf(rm0, __shfl_xor_sync(0xffffffffu, rm0, 2, 4));
        rm1 = fmaxf(rm1, __shfl_xor_sync(0xffffffffu, rm1, 1, 4));
        rm1 = fmaxf(rm1, __shfl_xor_sync(0xffffffffu, rm1, 2, 4));

        const float mn0 = fmaxf(m0, rm0);
        const float mn1 = fmaxf(m1, rm1);
        const float cr0 = __expf(m0 - mn0);
        const float cr1 = __expf(m1 - mn1);

        float ps0 = 0.0f, ps1 = 0.0f;
        #pragma unroll
        for (int nt = 0; nt < 8; nt++) {
            const float e0 = __expf(sc[nt][0] - mn0);
            const float e1 = __expf(sc[nt][1] - mn0);
            const float e2 = __expf(sc[nt][2] - mn1);
            const float e3 = __expf(sc[nt][3] - mn1);
            sc[nt][0] = e0; sc[nt][1] = e1; sc[nt][2] = e2; sc[nt][3] = e3;
            ps0 += e0 + e1;
            ps1 += e2 + e3;
        }
        ps0 += __shfl_xor_sync(0xffffffffu, ps0, 1, 4);
        ps0 += __shfl_xor_sync(0xffffffffu, ps0, 2, 4);
        ps1 += __shfl_xor_sync(0xffffffffu, ps1, 1, 4);
        ps1 += __shfl_xor_sync(0xffffffffu, ps1, 2, 4);

        l0 = l0 * cr0 + ps0;  m0 = mn0;
        l1 = l1 * cr1 + ps1;  m1 = mn1;

        #pragma unroll
        for (int nt = 0; nt < 8; nt++) {
            oc[nt][0] *= cr0; oc[nt][1] *= cr0;
            oc[nt][2] *= cr1; oc[nt][3] *= cr1;
        }

        __syncwarp();
        #pragma unroll
        for (int nt = 0; nt < 8; nt++) {
            float2 p01; p01.x = sc[nt][0]; p01.y = sc[nt][1];
            float2 p23; p23.x = sc[nt][2]; p23.y = sc[nt][3];
            *(float2*)&pw[gi * AT_LDP + nt * 8 + 2 * t4]       = p01;
            *(float2*)&pw[(gi + 8) * AT_LDP + nt * 8 + 2 * t4] = p23;
        }
        __syncwarp();

        #pragma unroll
        for (int kc = 0; kc < 8; kc++) {
            uint32_t ah[4], al[4];
            split_tf32(pw[gi * AT_LDP + kc * 8 + t4],           ah[0], al[0]);
            split_tf32(pw[(gi + 8) * AT_LDP + kc * 8 + t4],     ah[1], al[1]);
            split_tf32(pw[gi * AT_LDP + kc * 8 + t4 + 4],       ah[2], al[2]);
            split_tf32(pw[(gi + 8) * AT_LDP + kc * 8 + t4 + 4], ah[3], al[3]);

            uint32_t bh[8][2], bl[8][2];
            #pragma unroll
            for (int nt = 0; nt < 8; nt++) {
                split_tf32(Vs[(kc * 8 + t4) * AT_LDV + nt * 8 + gi],     bh[nt][0], bl[nt][0]);
                split_tf32(Vs[(kc * 8 + t4 + 4) * AT_LDV + nt * 8 + gi], bh[nt][1], bl[nt][1]);
            }
            #pragma unroll
            for (int nt = 0; nt < 8; nt++) mma_tf32(oc[nt], al, bh[nt][0], bh[nt][1]);
            #pragma unroll
            for (int nt = 0; nt < 8; nt++) mma_tf32(oc[nt], ah, bl[nt][0], bl[nt][1]);
            #pragma unroll
            for (int nt = 0; nt < 8; nt++) mma_tf32(oc[nt], ah, bh[nt][0], bh[nt][1]);
        }
    }

    const float inv0 = 1.0f / l0;
    const float inv1 = 1.0f / l1;
    float* op0 = O + ((size_t)(b * S_LEN + row0) * NH + h) * DH;
    float* op1 = op0 + 8 * rstride;
    #pragma unroll
    for (int nt = 0; nt < 8; nt++) {
        float2 w0, w1;
        w0.x = oc[nt][0] * inv0; w0.y = oc[nt][1] * inv0;
        w1.x = oc[nt][2] * inv1; w1.y = oc[nt][3] * inv1;
        *(float2*)(op0 + nt * 8 + 2 * t4) = w0;
        *(float2*)(op1 + nt * 8 + 2 * t4) = w1;
    }
}

// ---------------------------------------------------------------------------
// Launch
// ---------------------------------------------------------------------------
extern "C" void kernel_launch(void* const* d_in, const int* in_sizes, int n_in,
                              void* d_out, int out_size)
{
    const float* q    = (const float*)d_in[0];
    const float* k    = (const float*)d_in[1];
    const float* v    = (const float*)d_in[2];
    const unsigned char* kpm = (const unsigned char*)d_in[3];
    const float* Wq = (const float*)d_in[4];
    const float* bq = (const float*)d_in[5];
    const float* Wk = (const float*)d_in[6];
    const float* bk = (const float*)d_in[7];
    const float* Wv = (const float*)d_in[8];
    const float* bv = (const float*)d_in[9];
    const float* Wo = (const float*)d_in[10];
    const float* bo = (const float*)d_in[11];
    float* out = (float*)d_out;

    void *pQp, *pKp, *pVp, *pAo, *pWh, *pWl;
    cudaGetSymbolAddress(&pQp, g_Qp);
    cudaGetSymbolAddress(&pKp, g_Kp);
    cudaGetSymbolAddress(&pVp, g_Vp);
    cudaGetSymbolAddress(&pAo, g_Ao);
    cudaGetSymbolAddress(&pWh, g_Whp);
    cudaGetSymbolAddress(&pWl, g_Wlp);

    cudaFuncSetAttribute(attn_mma_kernel,
                         cudaFuncAttributeMaxDynamicSharedMemorySize, AT_SMEM);

    // 1) pre-split weights -> packed bf16x2 hi/lo slabs
    dim3 sgrid(DD / 1024, 4);
    split_weights_kernel<<<sgrid, 256>>>(Wq, Wk, Wv, Wo,
                                         (uint32_t*)pWh, (uint32_t*)pWl);

    // 2) fused Q/K/V projections (bf16 x3 tensor cores)
    dim3 ggrid(D_MODEL / 128, M_ROWS / 128, 3);   // (8, 64, 3)
    gemm3_bf16<<<ggrid, 256>>>(q, k, v,
                               (const uint32_t*)pWh, (const uint32_t*)pWl,
                               bq, bk, bv,
                               (float*)pQp, (float*)pKp, (float*)pVp, 0);

    // 3) attention (round-5 kernel, unchanged)
    dim3 agrid(S_LEN / 128, NH, BATCH);            // (8, 16, 8)
    attn_mma_kernel<<<agrid, 256, AT_SMEM>>>((const float*)pQp, (const float*)pKp,
                                             (const float*)pVp, kpm, (float*)pAo);

    // 4) output projection (weight slab 3)
    dim3 ogrid(D_MODEL / 128, M_ROWS / 128, 1);
    gemm3_bf16<<<ogrid, 256>>>((const float*)pAo, (const float*)pAo, (const float*)pAo,
                               (const uint32_t*)pWh, (const uint32_t*)pWl,
                               bo, bo, bo,
                               out, out, out, 3);
}

// round 8
// speedup vs baseline: 1.6887x; 1.1502x over previous
#include <cuda_runtime.h>
#include <cuda_bf16.h>
#include <cstdint>

// Problem constants (fixed by setup_inputs)
#define BATCH   8
#define S_LEN   1024
#define D_MODEL 1024
#define NH      16
#define DH      64
#define M_ROWS  (BATCH * S_LEN)   // 8192
#define DD      (D_MODEL * D_MODEL)
#define DU      (D_MODEL / 2)     // u32 (bf16x2) per row
#define MU      (M_ROWS * DU)     // u32 per activation slab

// ---------------------------------------------------------------------------
// Scratch (device globals — no allocations allowed)
// ---------------------------------------------------------------------------
__device__ float    g_Qp[M_ROWS * D_MODEL];
__device__ float    g_Kp[M_ROWS * D_MODEL];
__device__ float    g_Vp[M_ROWS * D_MODEL];
__device__ float    g_Ao[M_ROWS * D_MODEL];
__device__ uint32_t g_Whp[4 * DD / 2];   // packed bf16x2 hi of Wq,Wk,Wv,Wo
__device__ uint32_t g_Wlp[4 * DD / 2];   // packed bf16x2 lo
__device__ uint32_t g_Ahp[3 * MU];       // packed activations hi (q,k,v / Ao in slab 0)
__device__ uint32_t g_Alp[3 * MU];       // packed activations lo

// ---------------------------------------------------------------------------
// bf16 helpers (3xBF16: x = h + l; keep ah*bh + ah*bl + al*bh)
// ---------------------------------------------------------------------------
__device__ __forceinline__ uint32_t bpack(float x0, float x1) {
    __nv_bfloat162 t = __floats2bfloat162_rn(x0, x1);   // x0 -> low half
    return *reinterpret_cast<uint32_t*>(&t);
}
__device__ __forceinline__ void bsplit2(float x0, float x1, uint32_t& ph, uint32_t& pl) {
    const float h0 = __bfloat162float(__float2bfloat16(x0));
    const float h1 = __bfloat162float(__float2bfloat16(x1));
    ph = bpack(h0, h1);
    pl = bpack(x0 - h0, x1 - h1);
}
__device__ __forceinline__ void mma_bf16(float* c, const uint32_t* a, uint32_t b0, uint32_t b1) {
    asm volatile(
        "mma.sync.aligned.m16n8k16.row.col.f32.bf16.bf16.f32 "
        "{%0,%1,%2,%3}, {%4,%5,%6,%7}, {%8,%9}, {%0,%1,%2,%3};\n"
        : "+f"(c[0]), "+f"(c[1]), "+f"(c[2]), "+f"(c[3])
        : "r"(a[0]), "r"(a[1]), "r"(a[2]), "r"(a[3]), "r"(b0), "r"(b1));
}

// ---------------------------------------------------------------------------
// tf32 helpers (attention kernel)
// ---------------------------------------------------------------------------
__device__ __forceinline__ uint32_t f2tf32(float x) {
    uint32_t r;
    asm("cvt.rna.tf32.f32 %0, %1;" : "=r"(r) : "f"(x));
    return r;
}
__device__ __forceinline__ void split_tf32(float x, uint32_t& h, uint32_t& l) {
    h = f2tf32(x);
    l = f2tf32(x - __uint_as_float(h));
}
__device__ __forceinline__ void split_f(float x, float& h, float& l) {
    uint32_t hh = f2tf32(x);
    h = __uint_as_float(hh);
    l = __uint_as_float(f2tf32(x - h));
}
__device__ __forceinline__ void mma_tf32(float* c, const uint32_t* a, uint32_t b0, uint32_t b1) {
    asm volatile(
        "mma.sync.aligned.m16n8k8.row.col.f32.tf32.tf32.f32 "
        "{%0,%1,%2,%3}, {%4,%5,%6,%7}, {%8,%9}, {%0,%1,%2,%3};\n"
        : "+f"(c[0]), "+f"(c[1]), "+f"(c[2]), "+f"(c[3])
        : "r"(a[0]), "r"(a[1]), "r"(a[2]), "r"(a[3]), "r"(b0), "r"(b1));
}

// ---------------------------------------------------------------------------
// cp.async helpers
// ---------------------------------------------------------------------------
__device__ __forceinline__ void cpa16(uint32_t smaddr, const void* gptr) {
    asm volatile("cp.async.cg.shared.global [%0], [%1], 16;\n"
                 :: "r"(smaddr), "l"(gptr));
}
#define CP_COMMIT() asm volatile("cp.async.commit_group;\n" ::: "memory")
#define CP_WAIT1()  asm volatile("cp.async.wait_group 1;\n" ::: "memory")

// ---------------------------------------------------------------------------
// Pre-split: fp32 tensor -> packed bf16x2 hi/lo slabs.
// ---------------------------------------------------------------------------
__global__ void split_weights_kernel(
    const float* __restrict__ W0, const float* __restrict__ W1,
    const float* __restrict__ W2, const float* __restrict__ W3,
    uint32_t* __restrict__ Hp, uint32_t* __restrict__ Lp)
{
    const int z = blockIdx.y;
    const float* W = (z == 0) ? W0 : (z == 1) ? W1 : (z == 2) ? W2 : W3;
    const size_t fi = ((size_t)blockIdx.x * 256 + threadIdx.x) * 4;
    const size_t ui = (size_t)z * (DD / 2) + fi / 2;
    float4 x = *(const float4*)(W + fi);
    uint2 h2, l2;
    bsplit2(x.x, x.y, h2.x, l2.x);
    bsplit2(x.z, x.w, h2.y, l2.y);
    *(uint2*)(Hp + ui) = h2;
    *(uint2*)(Lp + ui) = l2;
}

// Activations: grid (MROWS*D/1024, nz); z selects source, writes slab z.
__global__ void split_acts_kernel(
    const float* __restrict__ X0, const float* __restrict__ X1,
    const float* __restrict__ X2,
    uint32_t* __restrict__ Hp, uint32_t* __restrict__ Lp)
{
    const int z = blockIdx.y;
    const float* X = (z == 0) ? X0 : (z == 1) ? X1 : X2;
    const size_t fi = ((size_t)blockIdx.x * 256 + threadIdx.x) * 4;
    const size_t ui = (size_t)z * MU + fi / 2;
    float4 x = *(const float4*)(X + fi);
    uint2 h2, l2;
    bsplit2(x.x, x.y, h2.x, l2.x);
    bsplit2(x.z, x.w, h2.y, l2.y);
    *(uint2*)(Hp + ui) = h2;
    *(uint2*)(Lp + ui) = l2;
}

// ---------------------------------------------------------------------------
// GEMM v4:  C[M,N] = A[M,K] @ W[N,K]^T + bias[N]   (NT, bf16 x3 tensor-core)
// All operands pre-split/packed bf16x2 in global. cp.async 2-stage pipeline.
// 128x128x32 CTA tile, 256 threads (8 warps, warp tile 32x64), 2 CTAs/SM.
// Smem rows: 16 u32 payload, stride 20 (80B, 16B-aligned rows; fragment
// reads bank-conflict-free: (20*gi + t4) % 32 is a permutation over gi).
// ---------------------------------------------------------------------------
#define GBK 32            // bf16 elements per k-tile
#define GKU 16            // u32 per row per tile
#define GLD 20            // smem row stride in u32
#define TILE_U32 (128 * GLD)        // 2560
#define STAGE_U32 (4 * TILE_U32)    // 10240
#define G4_SMEM (2 * STAGE_U32 * 4) // 81920 bytes

__global__ void __launch_bounds__(256, 2) gemm4_bf16(
    const uint32_t* __restrict__ Ahp, const uint32_t* __restrict__ Alp,
    const uint32_t* __restrict__ Whp, const uint32_t* __restrict__ Wlp,
    const float* __restrict__ b0, const float* __restrict__ b1, const float* __restrict__ b2,
    float* __restrict__ C0, float* __restrict__ C1, float* __restrict__ C2,
    int widx0)
{
    extern __shared__ uint32_t smu[];

    const int z = blockIdx.z;
    const float* bias = (z == 0) ? b0 : (z == 1) ? b1 : b2;
    float*       C    = (z == 0) ? C0 : (z == 1) ? C1 : C2;
    const uint32_t* Ah = Ahp + (size_t)z * MU;
    const uint32_t* Al = Alp + (size_t)z * MU;
    const uint32_t* Bh = Whp + (size_t)(widx0 + z) * (DD / 2);
    const uint32_t* Bl = Wlp + (size_t)(widx0 + z) * (DD / 2);

    const int tid  = threadIdx.x;
    const int lane = tid & 31;
    const int warp = tid >> 5;
    const int wm = warp & 3;           // m0 = wm*32
    const int wn = warp >> 2;          // n0 = wn*64
    const int gi = lane >> 2;
    const int t4 = lane & 3;

    const int bm = blockIdx.y * 128;
    const int bn = blockIdx.x * 128;

    // loader: row = tid/2, 8 u32 at uc per array (2 x cp.async 16B)
    const int lr = tid >> 1;
    const int uc = (tid & 1) * 8;
    const uint32_t* Ahg = Ah + (size_t)(bm + lr) * DU + uc;
    const uint32_t* Alg = Al + (size_t)(bm + lr) * DU + uc;
    const uint32_t* Bhg = Bh + (size_t)(bn + lr) * DU + uc;
    const uint32_t* Blg = Bl + (size_t)(bn + lr) * DU + uc;

    const uint32_t smbase = (uint32_t)__cvta_generic_to_shared(smu);
    const uint32_t rowoff = (lr * GLD + uc) * 4;   // byte offset within tile

    float acc[2][8][4];
    #pragma unroll
    for (int mt = 0; mt < 2; mt++)
        #pragma unroll
        for (int nt = 0; nt < 8; nt++)
            #pragma unroll
            for (int i = 0; i < 4; i++) acc[mt][nt][i] = 0.0f;

    // stage loader
    auto load_stage = [&](int st, int k0) {
        const int ku = k0 >> 1;
        const uint32_t sb = smbase + (uint32_t)st * (STAGE_U32 * 4) + rowoff;
        cpa16(sb,                      Ahg + ku);
        cpa16(sb + 16,                 Ahg + ku + 4);
        cpa16(sb + TILE_U32 * 4,       Alg + ku);
        cpa16(sb + TILE_U32 * 4 + 16,  Alg + ku + 4);
        cpa16(sb + TILE_U32 * 8,       Bhg + ku);
        cpa16(sb + TILE_U32 * 8 + 16,  Bhg + ku + 4);
        cpa16(sb + TILE_U32 * 12,      Blg + ku);
        cpa16(sb + TILE_U32 * 12 + 16, Blg + ku + 4);
    };

    const int ntiles = D_MODEL / GBK;   // 32
    load_stage(0, 0);
    CP_COMMIT();
    load_stage(1, GBK);
    CP_COMMIT();

    for (int i = 0; i < ntiles; i++) {
        CP_WAIT1();
        __syncthreads();

        const uint32_t* S   = smu + (i & 1) * STAGE_U32;
        const uint32_t* Ash = S;
        const uint32_t* Asl = S + TILE_U32;
        const uint32_t* Bsh = S + 2 * TILE_U32;
        const uint32_t* Bsl = S + 3 * TILE_U32;

        #pragma unroll
        for (int kk = 0; kk < GKU; kk += 8) {    // two k16 steps
            uint32_t ah[2][4], al[2][4];
            #pragma unroll
            for (int mt = 0; mt < 2; mt++) {
                const int r = wm * 32 + mt * 16 + gi;
                ah[mt][0] = Ash[r * GLD + kk + t4];
                al[mt][0] = Asl[r * GLD + kk + t4];
                ah[mt][1] = Ash[(r + 8) * GLD + kk + t4];
                al[mt][1] = Asl[(r + 8) * GLD + kk + t4];
                ah[mt][2] = Ash[r * GLD + kk + t4 + 4];
                al[mt][2] = Asl[r * GLD + kk + t4 + 4];
                ah[mt][3] = Ash[(r + 8) * GLD + kk + t4 + 4];
                al[mt][3] = Asl[(r + 8) * GLD + kk + t4 + 4];
            }
            #pragma unroll
            for (int nt = 0; nt < 8; nt++) {
                const int rb = wn * 64 + nt * 8 + gi;
                const uint32_t bh0 = Bsh[rb * GLD + kk + t4];
                const uint32_t bh1 = Bsh[rb * GLD + kk + t4 + 4];
                const uint32_t bl0 = Bsl[rb * GLD + kk + t4];
                const uint32_t bl1 = Bsl[rb * GLD + kk + t4 + 4];
                #pragma unroll
                for (int mt = 0; mt < 2; mt++) {
                    mma_bf16(acc[mt][nt], al[mt], bh0, bh1);
                    mma_bf16(acc[mt][nt], ah[mt], bl0, bl1);
                    mma_bf16(acc[mt][nt], ah[mt], bh0, bh1);
                }
            }
        }

        __syncthreads();
        if (i + 2 < ntiles) {
            load_stage(i & 1, (i + 2) * GBK);
            CP_COMMIT();
        }
    }

    #pragma unroll
    for (int nt = 0; nt < 8; nt++) {
        const int col = bn + wn * 64 + nt * 8 + 2 * t4;
        const float2 bb = *(const float2*)(bias + col);
        #pragma unroll
        for (int mt = 0; mt < 2; mt++) {
            const int row0 = bm + wm * 32 + mt * 16 + gi;
            float2 o0, o1;
            o0.x = acc[mt][nt][0] + bb.x; o0.y = acc[mt][nt][1] + bb.y;
            o1.x = acc[mt][nt][2] + bb.x; o1.y = acc[mt][nt][3] + bb.y;
            *(float2*)(C + (size_t)row0 * D_MODEL + col)       = o0;
            *(float2*)(C + (size_t)(row0 + 8) * D_MODEL + col) = o1;
        }
    }
}

// ---------------------------------------------------------------------------
// Tensor-core flash attention (tf32 x3) — round-6 version (pre-split K/V).
// Validated: rel_err bit-identical to round 5; est ~290us.
// ---------------------------------------------------------------------------
#define AT_LDK 64
#define AT_LDV 72
#define AT_LDP 68
#define AT_SMEM ((2*64*AT_LDK + 2*64*AT_LDV + 8*16*AT_LDP + 64) * 4)

__global__ void __launch_bounds__(256, 1) attn_mma_kernel(
    const float* __restrict__ Q, const float* __restrict__ K,
    const float* __restrict__ V, const unsigned char* __restrict__ kpm,
    float* __restrict__ O)
{
    extern __shared__ float sm[];
    float* Ksh  = sm;                          // 64 x 64 (swizzled), hi
    float* Ksl  = Ksh + 64 * AT_LDK;           // lo
    float* Vsh  = Ksl + 64 * AT_LDK;           // 64 x 72, hi
    float* Vsl  = Vsh + 64 * AT_LDV;           // lo
    float* Ps   = Vsl + 64 * AT_LDV;           // 8 warps x 16 x 68
    float* mneg = Ps + 8 * 16 * AT_LDP;        // 64

    const int b   = blockIdx.z;
    const int h   = blockIdx.y;
    const int qt  = gridDim.x - 1 - blockIdx.x;   // heavy tiles first
    const int tid = threadIdx.x;
    const int w    = tid >> 5;
    const int lane = tid & 31;
    const int gi = lane >> 2;
    const int t4 = lane & 3;

    const int q0   = qt * 128;
    const int row0 = q0 + w * 16 + gi;        // rows: row0, row0+8

    const float scale = 0.125f;               // 1/sqrt(64)
    const float NEG = -1e30f;
    const size_t rstride = (size_t)NH * DH;

    uint32_t qh[8][4], ql[8][4];
    {
        const float* qp0 = Q + ((size_t)(b * S_LEN + row0) * NH + h) * DH;
        const float* qp1 = qp0 + 8 * rstride;
        #pragma unroll
        for (int kc = 0; kc < 8; kc++) {
            split_tf32(qp0[kc * 8 + t4],     qh[kc][0], ql[kc][0]);
            split_tf32(qp1[kc * 8 + t4],     qh[kc][1], ql[kc][1]);
            split_tf32(qp0[kc * 8 + t4 + 4], qh[kc][2], ql[kc][2]);
            split_tf32(qp1[kc * 8 + t4 + 4], qh[kc][3], ql[kc][3]);
        }
    }

    float oc[8][4];
    #pragma unroll
    for (int nt = 0; nt < 8; nt++)
        #pragma unroll
        for (int i = 0; i < 4; i++) oc[nt][i] = 0.0f;
    float m0 = NEG, m1 = NEG, l0 = 0.0f, l1 = 0.0f;

    const int lr = tid >> 2;
    const int lc = (tid & 3) * 16;
    const int swz = (lr & 7) << 2;

    float* pw = Ps + w * 16 * AT_LDP;
    const int ktiles = 2 * qt + 2;

    for (int kt = 0; kt < ktiles; kt++) {
        const int k0 = kt * 64;
        __syncthreads();
        {
            const float* krow = K + ((size_t)(b * S_LEN + k0 + lr) * NH + h) * DH + lc;
            const float* vrow = V + ((size_t)(b * S_LEN + k0 + lr) * NH + h) * DH + lc;
            #pragma unroll
            for (int c = 0; c < 4; c++) {
                float4 kv = *(const float4*)(krow + 4 * c);
                float4 vv = *(const float4*)(vrow + 4 * c);
                float4 h4, l4;
                split_f(kv.x, h4.x, l4.x);
                split_f(kv.y, h4.y, l4.y);
                split_f(kv.z, h4.z, l4.z);
                split_f(kv.w, h4.w, l4.w);
                const int ko = lr * AT_LDK + ((lc + 4 * c) ^ swz);
                *(float4*)&Ksh[ko] = h4;
                *(float4*)&Ksl[ko] = l4;
                split_f(vv.x, h4.x, l4.x);
                split_f(vv.y, h4.y, l4.y);
                split_f(vv.z, h4.z, l4.z);
                split_f(vv.w, h4.w, l4.w);
                const int vo = lr * AT_LDV + lc + 4 * c;
                *(float4*)&Vsh[vo] = h4;
                *(float4*)&Vsl[vo] = l4;
            }
            if (tid < 64) mneg[tid] = kpm[b * S_LEN + k0 + tid] ? NEG : 0.0f;
        }
        __syncthreads();

        float sc[8][4];
        #pragma unroll
        for (int nt = 0; nt < 8; nt++)
            #pragma unroll
            for (int i = 0; i < 4; i++) sc[nt][i] = 0.0f;

        #pragma unroll
        for (int kc = 0; kc < 8; kc++) {
            uint32_t bh[8][2], bl[8][2];
            #pragma unroll
            for (int nt = 0; nt < 8; nt++) {
                const int krw = nt * 8 + gi;
                const int ks = (krw & 7) << 2;
                const int o0 = krw * AT_LDK + ((kc * 8 + t4) ^ ks);
                const int o1 = krw * AT_LDK + ((kc * 8 + t4 + 4) ^ ks);
                bh[nt][0] = __float_as_uint(Ksh[o0]);
                bl[nt][0] = __float_as_uint(Ksl[o0]);
                bh[nt][1] = __float_as_uint(Ksh[o1]);
                bl[nt][1] = __float_as_uint(Ksl[o1]);
            }
            #pragma unroll
            for (int nt = 0; nt < 8; nt++) mma_tf32(sc[nt], ql[kc], bh[nt][0], bh[nt][1]);
            #pragma unroll
            for (int nt = 0; nt < 8; nt++) mma_tf32(sc[nt], qh[kc], bl[nt][0], bl[nt][1]);
            #pragma unroll
            for (int nt = 0; nt < 8; nt++) mma_tf32(sc[nt], qh[kc], bh[nt][0], bh[nt][1]);
        }

        const bool needc = (k0 + 63) > row0;
        float rm0 = NEG, rm1 = NEG;
        #pragma unroll
        for (int nt = 0; nt < 8; nt++) {
            const int col = k0 + nt * 8 + 2 * t4;
            const float mg0 = mneg[nt * 8 + 2 * t4];
            const float mg1 = mneg[nt * 8 + 2 * t4 + 1];
            float v0 = sc[nt][0] * scale + mg0;
            float v1 = sc[nt][1] * scale + mg1;
            float v2 = sc[nt][2] * scale + mg0;
            float v3 = sc[nt][3] * scale + mg1;
            if (needc) {
                if (col     > row0)     v0 = NEG;
                if (col + 1 > row0)     v1 = NEG;
                if (col     > row0 + 8) v2 = NEG;
                if (col + 1 > row0 + 8) v3 = NEG;
            }
            sc[nt][0] = v0; sc[nt][1] = v1; sc[nt][2] = v2; sc[nt][3] = v3;
            rm0 = fmaxf(rm0, fmaxf(v0, v1));
            rm1 = fmaxf(rm1, fmaxf(v2, v3));
        }
        rm0 = fmaxf(rm0, __shfl_xor_sync(0xffffffffu, rm0, 1, 4));
        rm0 = fmaxf(rm0, __shfl_xor_sync(0xffffffffu, rm0, 2, 4));
        rm1 = fmaxf(rm1, __shfl_xor_sync(0xffffffffu, rm1, 1, 4));
        rm1 = fmaxf(rm1, __shfl_xor_sync(0xffffffffu, rm1, 2, 4));

        const float mn0 = fmaxf(m0, rm0);
        const float mn1 = fmaxf(m1, rm1);
        const float cr0 = __expf(m0 - mn0);
        const float cr1 = __expf(m1 - mn1);

        float ps0 = 0.0f, ps1 = 0.0f;
        #pragma unroll
        for (int nt = 0; nt < 8; nt++) {
            const float e0 = __expf(sc[nt][0] - mn0);
            const float e1 = __expf(sc[nt][1] - mn0);
            const float e2 = __expf(sc[nt][2] - mn1);
            const float e3 = __expf(sc[nt][3] - mn1);
            sc[nt][0] = e0; sc[nt][1] = e1; sc[nt][2] = e2; sc[nt][3] = e3;
            ps0 += e0 + e1;
            ps1 += e2 + e3;
        }
        ps0 += __shfl_xor_sync(0xffffffffu, ps0, 1, 4);
        ps0 += __shfl_xor_sync(0xffffffffu, ps0, 2, 4);
        ps1 += __shfl_xor_sync(0xffffffffu, ps1, 1, 4);
        ps1 += __shfl_xor_sync(0xffffffffu, ps1, 2, 4);

        l0 = l0 * cr0 + ps0;  m0 = mn0;
        l1 = l1 * cr1 + ps1;  m1 = mn1;

        #pragma unroll
        for (int nt = 0; nt < 8; nt++) {
            oc[nt][0] *= cr0; oc[nt][1] *= cr0;
            oc[nt][2] *= cr1; oc[nt][3] *= cr1;
        }

        __syncwarp();
        #pragma unroll
        for (int nt = 0; nt < 8; nt++) {
            float2 p01; p01.x = sc[nt][0]; p01.y = sc[nt][1];
            float2 p23; p23.x = sc[nt][2]; p23.y = sc[nt][3];
            *(float2*)&pw[gi * AT_LDP + nt * 8 + 2 * t4]       = p01;
            *(float2*)&pw[(gi + 8) * AT_LDP + nt * 8 + 2 * t4] = p23;
        }
        __syncwarp();

        #pragma unroll
        for (int kc = 0; kc < 8; kc++) {
            uint32_t ah[4], al[4];
            split_tf32(pw[gi * AT_LDP + kc * 8 + t4],           ah[0], al[0]);
            split_tf32(pw[(gi + 8) * AT_LDP + kc * 8 + t4],     ah[1], al[1]);
            split_tf32(pw[gi * AT_LDP + kc * 8 + t4 + 4],       ah[2], al[2]);
            split_tf32(pw[(gi + 8) * AT_LDP + kc * 8 + t4 + 4], ah[3], al[3]);

            uint32_t bh[8][2], bl[8][2];
            #pragma unroll
            for (int nt = 0; nt < 8; nt++) {
                const int o0 = (kc * 8 + t4) * AT_LDV + nt * 8 + gi;
                const int o1 = (kc * 8 + t4 + 4) * AT_LDV + nt * 8 + gi;
                bh[nt][0] = __float_as_uint(Vsh[o0]);
                bl[nt][0] = __float_as_uint(Vsl[o0]);
                bh[nt][1] = __float_as_uint(Vsh[o1]);
                bl[nt][1] = __float_as_uint(Vsl[o1]);
            }
            #pragma unroll
            for (int nt = 0; nt < 8; nt++) mma_tf32(oc[nt], al, bh[nt][0], bh[nt][1]);
            #pragma unroll
            for (int nt = 0; nt < 8; nt++) mma_tf32(oc[nt], ah, bl[nt][0], bl[nt][1]);
            #pragma unroll
            for (int nt = 0; nt < 8; nt++) mma_tf32(oc[nt], ah, bh[nt][0], bh[nt][1]);
        }
    }

    const float inv0 = 1.0f / l0;
    const float inv1 = 1.0f / l1;
    float* op0 = O + ((size_t)(b * S_LEN + row0) * NH + h) * DH;
    float* op1 = op0 + 8 * rstride;
    #pragma unroll
    for (int nt = 0; nt < 8; nt++) {
        float2 w0, w1;
        w0.x = oc[nt][0] * inv0; w0.y = oc[nt][1] * inv0;
        w1.x = oc[nt][2] * inv1; w1.y = oc[nt][3] * inv1;
        *(float2*)(op0 + nt * 8 + 2 * t4) = w0;
        *(float2*)(op1 + nt * 8 + 2 * t4) = w1;
    }
}

// ---------------------------------------------------------------------------
// Launch
// ---------------------------------------------------------------------------
extern "C" void kernel_launch(void* const* d_in, const int* in_sizes, int n_in,
                              void* d_out, int out_size)
{
    const float* q    = (const float*)d_in[0];
    const float* k    = (const float*)d_in[1];
    const float* v    = (const float*)d_in[2];
    const unsigned char* kpm = (const unsigned char*)d_in[3];
    const float* Wq = (const float*)d_in[4];
    const float* bq = (const float*)d_in[5];
    const float* Wk = (const float*)d_in[6];
    const float* bk = (const float*)d_in[7];
    const float* Wv = (const float*)d_in[8];
    const float* bv = (const float*)d_in[9];
    const float* Wo = (const float*)d_in[10];
    const float* bo = (const float*)d_in[11];
    float* out = (float*)d_out;

    void *pQp, *pKp, *pVp, *pAo, *pWh, *pWl, *pAh, *pAl;
    cudaGetSymbolAddress(&pQp, g_Qp);
    cudaGetSymbolAddress(&pKp, g_Kp);
    cudaGetSymbolAddress(&pVp, g_Vp);
    cudaGetSymbolAddress(&pAo, g_Ao);
    cudaGetSymbolAddress(&pWh, g_Whp);
    cudaGetSymbolAddress(&pWl, g_Wlp);
    cudaGetSymbolAddress(&pAh, g_Ahp);
    cudaGetSymbolAddress(&pAl, g_Alp);

    cudaFuncSetAttribute(attn_mma_kernel,
                         cudaFuncAttributeMaxDynamicSharedMemorySize, AT_SMEM);
    cudaFuncSetAttribute(gemm4_bf16,
                         cudaFuncAttributeMaxDynamicSharedMemorySize, G4_SMEM);

    // 1) pre-split weights + q/k/v activations -> packed bf16x2 hi/lo slabs
    dim3 wgrid(DD / 1024, 4);
    split_weights_kernel<<<wgrid, 256>>>(Wq, Wk, Wv, Wo,
                                         (uint32_t*)pWh, (uint32_t*)pWl);
    dim3 agrid_s((M_ROWS * D_MODEL) / 1024, 3);
    split_acts_kernel<<<agrid_s, 256>>>(q, k, v,
                                        (uint32_t*)pAh, (uint32_t*)pAl);

    // 2) fused Q/K/V projections (bf16 x3, cp.async pipelined)
    dim3 ggrid(D_MODEL / 128, M_ROWS / 128, 3);   // (8, 64, 3)
    gemm4_bf16<<<ggrid, 256, G4_SMEM>>>(
        (const uint32_t*)pAh, (const uint32_t*)pAl,
        (const uint32_t*)pWh, (const uint32_t*)pWl,
        bq, bk, bv,
        (float*)pQp, (float*)pKp, (float*)pVp, 0);

    // 3) attention
    dim3 agrid(S_LEN / 128, NH, BATCH);            // (8, 16, 8)
    attn_mma_kernel<<<agrid, 256, AT_SMEM>>>((const float*)pQp, (const float*)pKp,
                                             (const float*)pVp, kpm, (float*)pAo);

    // 4) split attn output into slab 0, then output projection (weight slab 3)
    dim3 ogrid_s((M_ROWS * D_MODEL) / 1024, 1);
    split_acts_kernel<<<ogrid_s, 256>>>((const float*)pAo, (const float*)pAo,
                                        (const float*)pAo,
                                        (uint32_t*)pAh, (uint32_t*)pAl);
    dim3 ogrid(D_MODEL / 128, M_ROWS / 128, 1);
    gemm4_bf16<<<ogrid, 256, G4_SMEM>>>(
        (const uint32_t*)pAh, (const uint32_t*)pAl,
        (const uint32_t*)pWh, (const uint32_t*)pWl,
        bo, bo, bo,
        out, out, out, 3);
}

// round 9
// speedup vs baseline: 1.8444x; 1.0922x over previous
#include <cuda_runtime.h>
#include <cuda_bf16.h>
#include <cstdint>

// Problem constants (fixed by setup_inputs)
#define BATCH   8
#define S_LEN   1024
#define D_MODEL 1024
#define NH      16
#define DH      64
#define M_ROWS  (BATCH * S_LEN)   // 8192
#define DD      (D_MODEL * D_MODEL)
#define DU      (D_MODEL / 2)     // u32 (bf16x2) per row
#define MU      (M_ROWS * DU)     // u32 per activation slab

// ---------------------------------------------------------------------------
// Scratch (device globals — no allocations allowed)
// ---------------------------------------------------------------------------
__device__ float    g_Qp[M_ROWS * D_MODEL];
__device__ float    g_Kp[M_ROWS * D_MODEL];
__device__ float    g_Vp[M_ROWS * D_MODEL];
__device__ float    g_Ao[M_ROWS * D_MODEL];
__device__ uint32_t g_Whp[4 * DD / 2];   // packed bf16x2 hi of Wq,Wk,Wv,Wo
__device__ uint32_t g_Wlp[4 * DD / 2];   // packed bf16x2 lo
__device__ uint32_t g_Ahp[3 * MU];       // packed activations hi
__device__ uint32_t g_Alp[3 * MU];       // packed activations lo

// ---------------------------------------------------------------------------
// bf16 helpers (3xBF16: x = h + l; keep ah*bh + ah*bl + al*bh)
// ---------------------------------------------------------------------------
__device__ __forceinline__ uint32_t bpack(float x0, float x1) {
    __nv_bfloat162 t = __floats2bfloat162_rn(x0, x1);   // x0 -> low half
    return *reinterpret_cast<uint32_t*>(&t);
}
__device__ __forceinline__ void bsplit2(float x0, float x1, uint32_t& ph, uint32_t& pl) {
    const float h0 = __bfloat162float(__float2bfloat16(x0));
    const float h1 = __bfloat162float(__float2bfloat16(x1));
    ph = bpack(h0, h1);
    pl = bpack(x0 - h0, x1 - h1);
}
__device__ __forceinline__ void mma_bf16(float* c, const uint32_t* a, uint32_t b0, uint32_t b1) {
    asm volatile(
        "mma.sync.aligned.m16n8k16.row.col.f32.bf16.bf16.f32 "
        "{%0,%1,%2,%3}, {%4,%5,%6,%7}, {%8,%9}, {%0,%1,%2,%3};\n"
        : "+f"(c[0]), "+f"(c[1]), "+f"(c[2]), "+f"(c[3])
        : "r"(a[0]), "r"(a[1]), "r"(a[2]), "r"(a[3]), "r"(b0), "r"(b1));
}

// ---------------------------------------------------------------------------
// cp.async helpers
// ---------------------------------------------------------------------------
__device__ __forceinline__ void cpa16(uint32_t smaddr, const void* gptr) {
    asm volatile("cp.async.cg.shared.global [%0], [%1], 16;\n"
                 :: "r"(smaddr), "l"(gptr));
}
#define CP_COMMIT() asm volatile("cp.async.commit_group;\n" ::: "memory")
#define CP_WAIT1()  asm volatile("cp.async.wait_group 1;\n" ::: "memory")

// ---------------------------------------------------------------------------
// Pre-split: fp32 tensor -> packed bf16x2 hi/lo slabs.
// ---------------------------------------------------------------------------
__global__ void split_weights_kernel(
    const float* __restrict__ W0, const float* __restrict__ W1,
    const float* __restrict__ W2, const float* __restrict__ W3,
    uint32_t* __restrict__ Hp, uint32_t* __restrict__ Lp)
{
    const int z = blockIdx.y;
    const float* W = (z == 0) ? W0 : (z == 1) ? W1 : (z == 2) ? W2 : W3;
    const size_t fi = ((size_t)blockIdx.x * 256 + threadIdx.x) * 4;
    const size_t ui = (size_t)z * (DD / 2) + fi / 2;
    float4 x = *(const float4*)(W + fi);
    uint2 h2, l2;
    bsplit2(x.x, x.y, h2.x, l2.x);
    bsplit2(x.z, x.w, h2.y, l2.y);
    *(uint2*)(Hp + ui) = h2;
    *(uint2*)(Lp + ui) = l2;
}

__global__ void split_acts_kernel(
    const float* __restrict__ X0, const float* __restrict__ X1,
    const float* __restrict__ X2,
    uint32_t* __restrict__ Hp, uint32_t* __restrict__ Lp)
{
    const int z = blockIdx.y;
    const float* X = (z == 0) ? X0 : (z == 1) ? X1 : X2;
    const size_t fi = ((size_t)blockIdx.x * 256 + threadIdx.x) * 4;
    const size_t ui = (size_t)z * MU + fi / 2;
    float4 x = *(const float4*)(X + fi);
    uint2 h2, l2;
    bsplit2(x.x, x.y, h2.x, l2.x);
    bsplit2(x.z, x.w, h2.y, l2.y);
    *(uint2*)(Hp + ui) = h2;
    *(uint2*)(Lp + ui) = l2;
}

// ---------------------------------------------------------------------------
// GEMM v4 (round-8, measured good):  C = A @ W^T + bias, bf16x3, cp.async.
// ---------------------------------------------------------------------------
#define GBK 32
#define GKU 16
#define GLD 20
#define TILE_U32 (128 * GLD)
#define STAGE_U32 (4 * TILE_U32)
#define G4_SMEM (2 * STAGE_U32 * 4)

__global__ void __launch_bounds__(256, 2) gemm4_bf16(
    const uint32_t* __restrict__ Ahp, const uint32_t* __restrict__ Alp,
    const uint32_t* __restrict__ Whp, const uint32_t* __restrict__ Wlp,
    const float* __restrict__ b0, const float* __restrict__ b1, const float* __restrict__ b2,
    float* __restrict__ C0, float* __restrict__ C1, float* __restrict__ C2,
    int widx0)
{
    extern __shared__ uint32_t smu[];

    const int z = blockIdx.z;
    const float* bias = (z == 0) ? b0 : (z == 1) ? b1 : b2;
    float*       C    = (z == 0) ? C0 : (z == 1) ? C1 : C2;
    const uint32_t* Ah = Ahp + (size_t)z * MU;
    const uint32_t* Al = Alp + (size_t)z * MU;
    const uint32_t* Bh = Whp + (size_t)(widx0 + z) * (DD / 2);
    const uint32_t* Bl = Wlp + (size_t)(widx0 + z) * (DD / 2);

    const int tid  = threadIdx.x;
    const int lane = tid & 31;
    const int warp = tid >> 5;
    const int wm = warp & 3;
    const int wn = warp >> 2;
    const int gi = lane >> 2;
    const int t4 = lane & 3;

    const int bm = blockIdx.y * 128;
    const int bn = blockIdx.x * 128;

    const int lr = tid >> 1;
    const int uc = (tid & 1) * 8;
    const uint32_t* Ahg = Ah + (size_t)(bm + lr) * DU + uc;
    const uint32_t* Alg = Al + (size_t)(bm + lr) * DU + uc;
    const uint32_t* Bhg = Bh + (size_t)(bn + lr) * DU + uc;
    const uint32_t* Blg = Bl + (size_t)(bn + lr) * DU + uc;

    const uint32_t smbase = (uint32_t)__cvta_generic_to_shared(smu);
    const uint32_t rowoff = (lr * GLD + uc) * 4;

    float acc[2][8][4];
    #pragma unroll
    for (int mt = 0; mt < 2; mt++)
        #pragma unroll
        for (int nt = 0; nt < 8; nt++)
            #pragma unroll
            for (int i = 0; i < 4; i++) acc[mt][nt][i] = 0.0f;

    auto load_stage = [&](int st, int k0) {
        const int ku = k0 >> 1;
        const uint32_t sb = smbase + (uint32_t)st * (STAGE_U32 * 4) + rowoff;
        cpa16(sb,                      Ahg + ku);
        cpa16(sb + 16,                 Ahg + ku + 4);
        cpa16(sb + TILE_U32 * 4,       Alg + ku);
        cpa16(sb + TILE_U32 * 4 + 16,  Alg + ku + 4);
        cpa16(sb + TILE_U32 * 8,       Bhg + ku);
        cpa16(sb + TILE_U32 * 8 + 16,  Bhg + ku + 4);
        cpa16(sb + TILE_U32 * 12,      Blg + ku);
        cpa16(sb + TILE_U32 * 12 + 16, Blg + ku + 4);
    };

    const int ntiles = D_MODEL / GBK;
    load_stage(0, 0);
    CP_COMMIT();
    load_stage(1, GBK);
    CP_COMMIT();

    for (int i = 0; i < ntiles; i++) {
        CP_WAIT1();
        __syncthreads();

        const uint32_t* S   = smu + (i & 1) * STAGE_U32;
        const uint32_t* Ash = S;
        const uint32_t* Asl = S + TILE_U32;
        const uint32_t* Bsh = S + 2 * TILE_U32;
        const uint32_t* Bsl = S + 3 * TILE_U32;

        #pragma unroll
        for (int kk = 0; kk < GKU; kk += 8) {
            uint32_t ah[2][4], al[2][4];
            #pragma unroll
            for (int mt = 0; mt < 2; mt++) {
                const int r = wm * 32 + mt * 16 + gi;
                ah[mt][0] = Ash[r * GLD + kk + t4];
                al[mt][0] = Asl[r * GLD + kk + t4];
                ah[mt][1] = Ash[(r + 8) * GLD + kk + t4];
                al[mt][1] = Asl[(r + 8) * GLD + kk + t4];
                ah[mt][2] = Ash[r * GLD + kk + t4 + 4];
                al[mt][2] = Asl[r * GLD + kk + t4 + 4];
                ah[mt][3] = Ash[(r + 8) * GLD + kk + t4 + 4];
                al[mt][3] = Asl[(r + 8) * GLD + kk + t4 + 4];
            }
            #pragma unroll
            for (int nt = 0; nt < 8; nt++) {
                const int rb = wn * 64 + nt * 8 + gi;
                const uint32_t bh0 = Bsh[rb * GLD + kk + t4];
                const uint32_t bh1 = Bsh[rb * GLD + kk + t4 + 4];
                const uint32_t bl0 = Bsl[rb * GLD + kk + t4];
                const uint32_t bl1 = Bsl[rb * GLD + kk + t4 + 4];
                #pragma unroll
                for (int mt = 0; mt < 2; mt++) {
                    mma_bf16(acc[mt][nt], al[mt], bh0, bh1);
                    mma_bf16(acc[mt][nt], ah[mt], bl0, bl1);
                    mma_bf16(acc[mt][nt], ah[mt], bh0, bh1);
                }
            }
        }

        __syncthreads();
        if (i + 2 < ntiles) {
            load_stage(i & 1, (i + 2) * GBK);
            CP_COMMIT();
        }
    }

    #pragma unroll
    for (int nt = 0; nt < 8; nt++) {
        const int col = bn + wn * 64 + nt * 8 + 2 * t4;
        const float2 bb = *(const float2*)(bias + col);
        #pragma unroll
        for (int mt = 0; mt < 2; mt++) {
            const int row0 = bm + wm * 32 + mt * 16 + gi;
            float2 o0, o1;
            o0.x = acc[mt][nt][0] + bb.x; o0.y = acc[mt][nt][1] + bb.y;
            o1.x = acc[mt][nt][2] + bb.x; o1.y = acc[mt][nt][3] + bb.y;
            *(float2*)(C + (size_t)row0 * D_MODEL + col)       = o0;
            *(float2*)(C + (size_t)(row0 + 8) * D_MODEL + col) = o1;
        }
    }
}

// ---------------------------------------------------------------------------
// Flash attention v3: bf16x3 tensor cores for BOTH QK^T and P.V.
// Grid (S/128, H, B), 256 threads = 8 warps; warp w owns 16 query rows.
// Smem (u32 units):
//  - Ks hi/lo: [64 keys][LDKU=36], packed dh pairs. Read bank (4gi+8kc+t4)%32
//    conflict-free.
//  - VsT hi/lo: [64 dh][LDVU=32] packed KEY pairs, XOR swizzle j^=(d&7)<<2.
//    Read bank (kc*8+t4)^(gi<<2) conflict-free.
//  - P hi/lo per warp: [16 rows][LDPU=36] packed key pairs (accumulator col
//    pairs pack directly). Read bank (4gi+8kc+t4)%32 conflict-free.
// ---------------------------------------------------------------------------
#define LDKU 36
#define LDVU 32
#define LDPU 36
#define AT_KSH 0
#define AT_KSL (64 * LDKU)                  // 2304
#define AT_VTH (2 * 64 * LDKU)              // 4608
#define AT_VTL (AT_VTH + 64 * LDVU)         // 6656
#define AT_PWH (AT_VTL + 64 * LDVU)         // 8704
#define AT_PWL (AT_PWH + 8 * 16 * LDPU)     // 13312
#define AT_MNEG (AT_PWL + 8 * 16 * LDPU)    // 17920
#define AT_SMEM ((AT_MNEG + 64) * 4)        // 71936 bytes

__global__ void __launch_bounds__(256, 1) attn_bf16_kernel(
    const float* __restrict__ Q, const float* __restrict__ K,
    const float* __restrict__ V, const unsigned char* __restrict__ kpm,
    float* __restrict__ O)
{
    extern __shared__ uint32_t su[];
    uint32_t* Ksh = su + AT_KSH;
    uint32_t* Ksl = su + AT_KSL;
    uint32_t* Vth = su + AT_VTH;
    uint32_t* Vtl = su + AT_VTL;
    float*    mneg = (float*)(su + AT_MNEG);

    const int b   = blockIdx.z;
    const int h   = blockIdx.y;
    const int qt  = gridDim.x - 1 - blockIdx.x;   // heavy tiles first
    const int tid = threadIdx.x;
    const int w    = tid >> 5;
    const int lane = tid & 31;
    const int gi = lane >> 2;
    const int t4 = lane & 3;

    const int q0   = qt * 128;
    const int row0 = q0 + w * 16 + gi;        // rows: row0, row0+8

    const float scale = 0.125f;               // 1/sqrt(64)
    const float NEG = -1e30f;
    const size_t rstride = (size_t)NH * DH;

    // ---- Q fragments, register-resident, pre-split packed bf16x2 ----
    uint32_t qh[4][4], ql[4][4];
    {
        const float* qp0 = Q + ((size_t)(b * S_LEN + row0) * NH + h) * DH;
        const float* qp1 = qp0 + 8 * rstride;
        #pragma unroll
        for (int kc = 0; kc < 4; kc++) {
            const int f0 = kc * 16 + 2 * t4;
            bsplit2(qp0[f0],     qp0[f0 + 1], qh[kc][0], ql[kc][0]);
            bsplit2(qp1[f0],     qp1[f0 + 1], qh[kc][1], ql[kc][1]);
            bsplit2(qp0[f0 + 8], qp0[f0 + 9], qh[kc][2], ql[kc][2]);
            bsplit2(qp1[f0 + 8], qp1[f0 + 9], qh[kc][3], ql[kc][3]);
        }
    }

    float oc[8][4];
    #pragma unroll
    for (int nt = 0; nt < 8; nt++)
        #pragma unroll
        for (int i = 0; i < 4; i++) oc[nt][i] = 0.0f;
    float m0 = NEG, m1 = NEG, l0 = 0.0f, l1 = 0.0f;

    // tile loader mapping: key = tid/4, 16 dims at (tid&3)*16
    const int lr = tid >> 2;
    const int lc = (tid & 3) * 16;

    uint32_t* pwh = su + AT_PWH + w * 16 * LDPU;
    uint32_t* pwl = su + AT_PWL + w * 16 * LDPU;
    const int ktiles = 2 * qt + 2;

    for (int kt = 0; kt < ktiles; kt++) {
        const int k0 = kt * 64;
        __syncthreads();
        {
            const float* krow = K + ((size_t)(b * S_LEN + k0 + lr) * NH + h) * DH + lc;
            const float* vrow = V + ((size_t)(b * S_LEN + k0 + lr) * NH + h) * DH + lc;
            __nv_bfloat16* vth16 = (__nv_bfloat16*)Vth;
            __nv_bfloat16* vtl16 = (__nv_bfloat16*)Vtl;
            #pragma unroll
            for (int c = 0; c < 4; c++) {
                // K: pack dh pairs into [key][u32]
                float4 kv = *(const float4*)(krow + 4 * c);
                uint32_t h01, l01, h23, l23;
                bsplit2(kv.x, kv.y, h01, l01);
                bsplit2(kv.z, kv.w, h23, l23);
                const int kw = lr * LDKU + lc / 2 + 2 * c;
                Ksh[kw] = h01; Ksh[kw + 1] = h23;
                Ksl[kw] = l01; Ksl[kw + 1] = l23;
                // V: transposed scalar bf16 stores into swizzled [dh][keypair]
                float4 vv = *(const float4*)(vrow + 4 * c);
                const float vf[4] = {vv.x, vv.y, vv.z, vv.w};
                #pragma unroll
                for (int e = 0; e < 4; e++) {
                    const int d = lc + 4 * c + e;
                    const float f = vf[e];
                    const float fh = __bfloat162float(__float2bfloat16(f));
                    const int widx = d * LDVU + ((lr >> 1) ^ ((d & 7) << 2));
                    vth16[widx * 2 + (lr & 1)] = __float2bfloat16(fh);
                    vtl16[widx * 2 + (lr & 1)] = __float2bfloat16(f - fh);
                }
            }
            if (tid < 64) mneg[tid] = kpm[b * S_LEN + k0 + tid] ? NEG : 0.0f;
        }
        __syncthreads();

        // ---- S = Q K^T (bf16 x3) ----
        float sc[8][4];
        #pragma unroll
        for (int nt = 0; nt < 8; nt++)
            #pragma unroll
            for (int i = 0; i < 4; i++) sc[nt][i] = 0.0f;

        #pragma unroll
        for (int kc = 0; kc < 4; kc++) {
            uint32_t bh[8][2], bl[8][2];
            #pragma unroll
            for (int nt = 0; nt < 8; nt++) {
                const int kr = (nt * 8 + gi) * LDKU + kc * 8 + t4;
                bh[nt][0] = Ksh[kr];
                bh[nt][1] = Ksh[kr + 4];
                bl[nt][0] = Ksl[kr];
                bl[nt][1] = Ksl[kr + 4];
            }
            #pragma unroll
            for (int nt = 0; nt < 8; nt++) mma_bf16(sc[nt], ql[kc], bh[nt][0], bh[nt][1]);
            #pragma unroll
            for (int nt = 0; nt < 8; nt++) mma_bf16(sc[nt], qh[kc], bl[nt][0], bl[nt][1]);
            #pragma unroll
            for (int nt = 0; nt < 8; nt++) mma_bf16(sc[nt], qh[kc], bh[nt][0], bh[nt][1]);
        }

        // ---- scale + masks + online softmax ----
        const bool needc = (k0 + 63) > row0;
        float rm0 = NEG, rm1 = NEG;
        #pragma unroll
        for (int nt = 0; nt < 8; nt++) {
            const int col = k0 + nt * 8 + 2 * t4;
            const float mg0 = mneg[nt * 8 + 2 * t4];
            const float mg1 = mneg[nt * 8 + 2 * t4 + 1];
            float v0 = sc[nt][0] * scale + mg0;
            float v1 = sc[nt][1] * scale + mg1;
            float v2 = sc[nt][2] * scale + mg0;
            float v3 = sc[nt][3] * scale + mg1;
            if (needc) {
                if (col     > row0)     v0 = NEG;
                if (col + 1 > row0)     v1 = NEG;
                if (col     > row0 + 8) v2 = NEG;
                if (col + 1 > row0 + 8) v3 = NEG;
            }
            sc[nt][0] = v0; sc[nt][1] = v1; sc[nt][2] = v2; sc[nt][3] = v3;
            rm0 = fmaxf(rm0, fmaxf(v0, v1));
            rm1 = fmaxf(rm1, fmaxf(v2, v3));
        }
        rm0 = fmaxf(rm0, __shfl_xor_sync(0xffffffffu, rm0, 1, 4));
        rm0 = fmaxf(rm0, __shfl_xor_sync(0xffffffffu, rm0, 2, 4));
        rm1 = fmaxf(rm1, __shfl_xor_sync(0xffffffffu, rm1, 1, 4));
        rm1 = fmaxf(rm1, __shfl_xor_sync(0xffffffffu, rm1, 2, 4));

        const float mn0 = fmaxf(m0, rm0);
        const float mn1 = fmaxf(m1, rm1);
        const float cr0 = __expf(m0 - mn0);
        const float cr1 = __expf(m1 - mn1);

        float ps0 = 0.0f, ps1 = 0.0f;
        #pragma unroll
        for (int nt = 0; nt < 8; nt++) {
            const float e0 = __expf(sc[nt][0] - mn0);
            const float e1 = __expf(sc[nt][1] - mn0);
            const float e2 = __expf(sc[nt][2] - mn1);
            const float e3 = __expf(sc[nt][3] - mn1);
            sc[nt][0] = e0; sc[nt][1] = e1; sc[nt][2] = e2; sc[nt][3] = e3;
            ps0 += e0 + e1;
            ps1 += e2 + e3;
        }
        ps0 += __shfl_xor_sync(0xffffffffu, ps0, 1, 4);
        ps0 += __shfl_xor_sync(0xffffffffu, ps0, 2, 4);
        ps1 += __shfl_xor_sync(0xffffffffu, ps1, 1, 4);
        ps1 += __shfl_xor_sync(0xffffffffu, ps1, 2, 4);

        l0 = l0 * cr0 + ps0;  m0 = mn0;
        l1 = l1 * cr1 + ps1;  m1 = mn1;

        #pragma unroll
        for (int nt = 0; nt < 8; nt++) {
            oc[nt][0] *= cr0; oc[nt][1] *= cr0;
            oc[nt][2] *= cr1; oc[nt][3] *= cr1;
        }

        // ---- P -> per-warp smem, packed bf16x2 hi/lo (col pairs = k pairs) ----
        __syncwarp();
        #pragma unroll
        for (int nt = 0; nt < 8; nt++) {
            uint32_t ph, pl;
            bsplit2(sc[nt][0], sc[nt][1], ph, pl);
            pwh[gi * LDPU + nt * 4 + t4] = ph;
            pwl[gi * LDPU + nt * 4 + t4] = pl;
            bsplit2(sc[nt][2], sc[nt][3], ph, pl);
            pwh[(gi + 8) * LDPU + nt * 4 + t4] = ph;
            pwl[(gi + 8) * LDPU + nt * 4 + t4] = pl;
        }
        __syncwarp();

        // ---- O += P V (bf16 x3) ----
        #pragma unroll
        for (int kc = 0; kc < 4; kc++) {
            uint32_t ah[4], al[4];
            ah[0] = pwh[gi * LDPU + kc * 8 + t4];
            al[0] = pwl[gi * LDPU + kc * 8 + t4];
            ah[1] = pwh[(gi + 8) * LDPU + kc * 8 + t4];
            al[1] = pwl[(gi + 8) * LDPU + kc * 8 + t4];
            ah[2] = pwh[gi * LDPU + kc * 8 + t4 + 4];
            al[2] = pwl[gi * LDPU + kc * 8 + t4 + 4];
            ah[3] = pwh[(gi + 8) * LDPU + kc * 8 + t4 + 4];
            al[3] = pwl[(gi + 8) * LDPU + kc * 8 + t4 + 4];

            uint32_t bh[8][2], bl[8][2];
            #pragma unroll
            for (int nt = 0; nt < 8; nt++) {
                const int d = nt * 8 + gi;
                const int o0 = d * LDVU + ((kc * 8 + t4) ^ (gi << 2));
                const int o1 = d * LDVU + ((kc * 8 + t4 + 4) ^ (gi << 2));
                bh[nt][0] = Vth[o0];
                bh[nt][1] = Vth[o1];
                bl[nt][0] = Vtl[o0];
                bl[nt][1] = Vtl[o1];
            }
            #pragma unroll
            for (int nt = 0; nt < 8; nt++) mma_bf16(oc[nt], al, bh[nt][0], bh[nt][1]);
            #pragma unroll
            for (int nt = 0; nt < 8; nt++) mma_bf16(oc[nt], ah, bl[nt][0], bl[nt][1]);
            #pragma unroll
            for (int nt = 0; nt < 8; nt++) mma_bf16(oc[nt], ah, bh[nt][0], bh[nt][1]);
        }
    }

    // ---- normalize + store ----
    const float inv0 = 1.0f / l0;
    const float inv1 = 1.0f / l1;
    float* op0 = O + ((size_t)(b * S_LEN + row0) * NH + h) * DH;
    float* op1 = op0 + 8 * rstride;
    #pragma unroll
    for (int nt = 0; nt < 8; nt++) {
        float2 w0, w1;
        w0.x = oc[nt][0] * inv0; w0.y = oc[nt][1] * inv0;
        w1.x = oc[nt][2] * inv1; w1.y = oc[nt][3] * inv1;
        *(float2*)(op0 + nt * 8 + 2 * t4) = w0;
        *(float2*)(op1 + nt * 8 + 2 * t4) = w1;
    }
}

// ---------------------------------------------------------------------------
// Launch
// ---------------------------------------------------------------------------
extern "C" void kernel_launch(void* const* d_in, const int* in_sizes, int n_in,
                              void* d_out, int out_size)
{
    const float* q    = (const float*)d_in[0];
    const float* k    = (const float*)d_in[1];
    const float* v    = (const float*)d_in[2];
    const unsigned char* kpm = (const unsigned char*)d_in[3];
    const float* Wq = (const float*)d_in[4];
    const float* bq = (const float*)d_in[5];
    const float* Wk = (const float*)d_in[6];
    const float* bk = (const float*)d_in[7];
    const float* Wv = (const float*)d_in[8];
    const float* bv = (const float*)d_in[9];
    const float* Wo = (const float*)d_in[10];
    const float* bo = (const float*)d_in[11];
    float* out = (float*)d_out;

    void *pQp, *pKp, *pVp, *pAo, *pWh, *pWl, *pAh, *pAl;
    cudaGetSymbolAddress(&pQp, g_Qp);
    cudaGetSymbolAddress(&pKp, g_Kp);
    cudaGetSymbolAddress(&pVp, g_Vp);
    cudaGetSymbolAddress(&pAo, g_Ao);
    cudaGetSymbolAddress(&pWh, g_Whp);
    cudaGetSymbolAddress(&pWl, g_Wlp);
    cudaGetSymbolAddress(&pAh, g_Ahp);
    cudaGetSymbolAddress(&pAl, g_Alp);

    cudaFuncSetAttribute(attn_bf16_kernel,
                         cudaFuncAttributeMaxDynamicSharedMemorySize, AT_SMEM);
    cudaFuncSetAttribute(gemm4_bf16,
                         cudaFuncAttributeMaxDynamicSharedMemorySize, G4_SMEM);

    // 1) pre-split weights + q/k/v activations -> packed bf16x2 hi/lo slabs
    dim3 wgrid(DD / 1024, 4);
    split_weights_kernel<<<wgrid, 256>>>(Wq, Wk, Wv, Wo,
                                         (uint32_t*)pWh, (uint32_t*)pWl);
    dim3 agrid_s((M_ROWS * D_MODEL) / 1024, 3);
    split_acts_kernel<<<agrid_s, 256>>>(q, k, v,
                                        (uint32_t*)pAh, (uint32_t*)pAl);

    // 2) fused Q/K/V projections (bf16 x3, cp.async pipelined)
    dim3 ggrid(D_MODEL / 128, M_ROWS / 128, 3);   // (8, 64, 3)
    gemm4_bf16<<<ggrid, 256, G4_SMEM>>>(
        (const uint32_t*)pAh, (const uint32_t*)pAl,
        (const uint32_t*)pWh, (const uint32_t*)pWl,
        bq, bk, bv,
        (float*)pQp, (float*)pKp, (float*)pVp, 0);

    // 3) attention (bf16 x3)
    dim3 agrid(S_LEN / 128, NH, BATCH);            // (8, 16, 8)
    attn_bf16_kernel<<<agrid, 256, AT_SMEM>>>((const float*)pQp, (const float*)pKp,
                                              (const float*)pVp, kpm, (float*)pAo);

    // 4) split attn output into slab 0, then output projection (weight slab 3)
    dim3 ogrid_s((M_ROWS * D_MODEL) / 1024, 1);
    split_acts_kernel<<<ogrid_s, 256>>>((const float*)pAo, (const float*)pAo,
                                        (const float*)pAo,
                                        (uint32_t*)pAh, (uint32_t*)pAl);
    dim3 ogrid(D_MODEL / 128, M_ROWS / 128, 1);
    gemm4_bf16<<<ogrid, 256, G4_SMEM>>>(
        (const uint32_t*)pAh, (const uint32_t*)pAl,
        (const uint32_t*)pWh, (const uint32_t*)pWl,
        bo, bo, bo,
        out, out, out, 3);
}

// round 10
// speedup vs baseline: 1.9731x; 1.0698x over previous
#include <cuda_runtime.h>
#include <cuda_bf16.h>
#include <cstdint>

// Problem constants (fixed by setup_inputs)
#define BATCH   8
#define S_LEN   1024
#define D_MODEL 1024
#define NH      16
#define DH      64
#define M_ROWS  (BATCH * S_LEN)   // 8192
#define DD      (D_MODEL * D_MODEL)
#define DU      (D_MODEL / 2)     // u32 (bf16x2) per row
#define MU      (M_ROWS * DU)     // u32 per activation slab
#define SU2     (S_LEN / 2)       // key-pairs per sequence

// ---------------------------------------------------------------------------
// Scratch (device globals — no allocations allowed)
// ---------------------------------------------------------------------------
__device__ uint32_t g_Ahp[3 * MU];   // packed raw q,k,v (inputs) hi
__device__ uint32_t g_Alp[3 * MU];   // lo
__device__ uint32_t g_Whp[4 * DD / 2];
__device__ uint32_t g_Wlp[4 * DD / 2];
__device__ uint32_t g_Qh[MU], g_Ql[MU];          // projected Q packed
__device__ uint32_t g_Kh[MU], g_Kl[MU];          // projected K packed
__device__ uint32_t g_VtH[MU], g_VtL[MU];        // projected V, transposed per (b,h): [dh][key-pair]
__device__ uint32_t g_Oh[MU], g_Ol[MU];          // attention output packed

// ---------------------------------------------------------------------------
// bf16 helpers (3xBF16: x = h + l; keep ah*bh + ah*bl + al*bh)
// ---------------------------------------------------------------------------
__device__ __forceinline__ uint32_t bpack(float x0, float x1) {
    __nv_bfloat162 t = __floats2bfloat162_rn(x0, x1);   // x0 -> low half
    return *reinterpret_cast<uint32_t*>(&t);
}
__device__ __forceinline__ void bsplit2(float x0, float x1, uint32_t& ph, uint32_t& pl) {
    const float h0 = __bfloat162float(__float2bfloat16(x0));
    const float h1 = __bfloat162float(__float2bfloat16(x1));
    ph = bpack(h0, h1);
    pl = bpack(x0 - h0, x1 - h1);
}
__device__ __forceinline__ void mma_bf16(float* c, const uint32_t* a, uint32_t b0, uint32_t b1) {
    asm volatile(
        "mma.sync.aligned.m16n8k16.row.col.f32.bf16.bf16.f32 "
        "{%0,%1,%2,%3}, {%4,%5,%6,%7}, {%8,%9}, {%0,%1,%2,%3};\n"
        : "+f"(c[0]), "+f"(c[1]), "+f"(c[2]), "+f"(c[3])
        : "r"(a[0]), "r"(a[1]), "r"(a[2]), "r"(a[3]), "r"(b0), "r"(b1));
}

// ---------------------------------------------------------------------------
// cp.async helpers
// ---------------------------------------------------------------------------
__device__ __forceinline__ void cpa16(uint32_t smaddr, const void* gptr) {
    asm volatile("cp.async.cg.shared.global [%0], [%1], 16;\n"
                 :: "r"(smaddr), "l"(gptr));
}
#define CP_COMMIT() asm volatile("cp.async.commit_group;\n" ::: "memory")
#define CP_WAIT1()  asm volatile("cp.async.wait_group 1;\n" ::: "memory")
#define CP_WAIT0()  asm volatile("cp.async.wait_group 0;\n" ::: "memory")

// ---------------------------------------------------------------------------
// Pre-split kernels (fp32 -> packed bf16x2 hi/lo)
// ---------------------------------------------------------------------------
__global__ void split_weights_kernel(
    const float* __restrict__ W0, const float* __restrict__ W1,
    const float* __restrict__ W2, const float* __restrict__ W3,
    uint32_t* __restrict__ Hp, uint32_t* __restrict__ Lp)
{
    const int z = blockIdx.y;
    const float* W = (z == 0) ? W0 : (z == 1) ? W1 : (z == 2) ? W2 : W3;
    const size_t fi = ((size_t)blockIdx.x * 256 + threadIdx.x) * 4;
    const size_t ui = (size_t)z * (DD / 2) + fi / 2;
    float4 x = *(const float4*)(W + fi);
    uint2 h2, l2;
    bsplit2(x.x, x.y, h2.x, l2.x);
    bsplit2(x.z, x.w, h2.y, l2.y);
    *(uint2*)(Hp + ui) = h2;
    *(uint2*)(Lp + ui) = l2;
}

__global__ void split_acts_kernel(
    const float* __restrict__ X0, const float* __restrict__ X1,
    const float* __restrict__ X2,
    uint32_t* __restrict__ Hp, uint32_t* __restrict__ Lp)
{
    const int z = blockIdx.y;
    const float* X = (z == 0) ? X0 : (z == 1) ? X1 : X2;
    const size_t fi = ((size_t)blockIdx.x * 256 + threadIdx.x) * 4;
    const size_t ui = (size_t)z * MU + fi / 2;
    float4 x = *(const float4*)(X + fi);
    uint2 h2, l2;
    bsplit2(x.x, x.y, h2.x, l2.x);
    bsplit2(x.z, x.w, h2.y, l2.y);
    *(uint2*)(Hp + ui) = h2;
    *(uint2*)(Lp + ui) = l2;
}

// ---------------------------------------------------------------------------
// GEMM v5:  C = A @ W^T + bias, bf16x3, cp.async 2-stage.
// Epilogue modes (QKV launch, outproj=0):
//   z=0 -> packed Q [token][dhpair], z=1 -> packed K, z=2 -> packed V transposed
// Out-proj launch (outproj=1): fp32 to Cout.
// ---------------------------------------------------------------------------
#define GBK 32
#define GKU 16
#define GLD 20
#define TILE_U32 (128 * GLD)
#define STAGE_U32 (4 * TILE_U32)
#define G4_SMEM (2 * STAGE_U32 * 4)

__global__ void __launch_bounds__(256, 2) gemm5_bf16(
    const uint32_t* __restrict__ Ahp, const uint32_t* __restrict__ Alp,
    const uint32_t* __restrict__ Whp, const uint32_t* __restrict__ Wlp,
    const float* __restrict__ b0, const float* __restrict__ b1, const float* __restrict__ b2,
    uint32_t* __restrict__ QhO, uint32_t* __restrict__ QlO,
    uint32_t* __restrict__ KhO, uint32_t* __restrict__ KlO,
    uint32_t* __restrict__ VtHO, uint32_t* __restrict__ VtLO,
    float* __restrict__ Cout,
    int widx0, int outproj)
{
    extern __shared__ uint32_t smu[];

    const int z = blockIdx.z;
    const float* bias = (z == 0) ? b0 : (z == 1) ? b1 : b2;
    const uint32_t* Ah = Ahp + (size_t)z * MU;
    const uint32_t* Al = Alp + (size_t)z * MU;
    const uint32_t* Bh = Whp + (size_t)(widx0 + z) * (DD / 2);
    const uint32_t* Bl = Wlp + (size_t)(widx0 + z) * (DD / 2);

    const int tid  = threadIdx.x;
    const int lane = tid & 31;
    const int warp = tid >> 5;
    const int wm = warp & 3;
    const int wn = warp >> 2;
    const int gi = lane >> 2;
    const int t4 = lane & 3;

    const int bm = blockIdx.y * 128;
    const int bn = blockIdx.x * 128;

    const int lr = tid >> 1;
    const int uc = (tid & 1) * 8;
    const uint32_t* Ahg = Ah + (size_t)(bm + lr) * DU + uc;
    const uint32_t* Alg = Al + (size_t)(bm + lr) * DU + uc;
    const uint32_t* Bhg = Bh + (size_t)(bn + lr) * DU + uc;
    const uint32_t* Blg = Bl + (size_t)(bn + lr) * DU + uc;

    const uint32_t smbase = (uint32_t)__cvta_generic_to_shared(smu);
    const uint32_t rowoff = (lr * GLD + uc) * 4;

    float acc[2][8][4];
    #pragma unroll
    for (int mt = 0; mt < 2; mt++)
        #pragma unroll
        for (int nt = 0; nt < 8; nt++)
            #pragma unroll
            for (int i = 0; i < 4; i++) acc[mt][nt][i] = 0.0f;

    auto load_stage = [&](int st, int k0) {
        const int ku = k0 >> 1;
        const uint32_t sb = smbase + (uint32_t)st * (STAGE_U32 * 4) + rowoff;
        cpa16(sb,                      Ahg + ku);
        cpa16(sb + 16,                 Ahg + ku + 4);
        cpa16(sb + TILE_U32 * 4,       Alg + ku);
        cpa16(sb + TILE_U32 * 4 + 16,  Alg + ku + 4);
        cpa16(sb + TILE_U32 * 8,       Bhg + ku);
        cpa16(sb + TILE_U32 * 8 + 16,  Bhg + ku + 4);
        cpa16(sb + TILE_U32 * 12,      Blg + ku);
        cpa16(sb + TILE_U32 * 12 + 16, Blg + ku + 4);
    };

    const int ntiles = D_MODEL / GBK;
    load_stage(0, 0);
    CP_COMMIT();
    load_stage(1, GBK);
    CP_COMMIT();

    for (int i = 0; i < ntiles; i++) {
        if (i + 1 < ntiles) CP_WAIT1(); else CP_WAIT0();
        __syncthreads();

        const uint32_t* S   = smu + (i & 1) * STAGE_U32;
        const uint32_t* Ash = S;
        const uint32_t* Asl = S + TILE_U32;
        const uint32_t* Bsh = S + 2 * TILE_U32;
        const uint32_t* Bsl = S + 3 * TILE_U32;

        #pragma unroll
        for (int kk = 0; kk < GKU; kk += 8) {
            uint32_t ah[2][4], al[2][4];
            #pragma unroll
            for (int mt = 0; mt < 2; mt++) {
                const int r = wm * 32 + mt * 16 + gi;
                ah[mt][0] = Ash[r * GLD + kk + t4];
                al[mt][0] = Asl[r * GLD + kk + t4];
                ah[mt][1] = Ash[(r + 8) * GLD + kk + t4];
                al[mt][1] = Asl[(r + 8) * GLD + kk + t4];
                ah[mt][2] = Ash[r * GLD + kk + t4 + 4];
                al[mt][2] = Asl[r * GLD + kk + t4 + 4];
                ah[mt][3] = Ash[(r + 8) * GLD + kk + t4 + 4];
                al[mt][3] = Asl[(r + 8) * GLD + kk + t4 + 4];
            }
            #pragma unroll
            for (int nt = 0; nt < 8; nt++) {
                const int rb = wn * 64 + nt * 8 + gi;
                const uint32_t bh0 = Bsh[rb * GLD + kk + t4];
                const uint32_t bh1 = Bsh[rb * GLD + kk + t4 + 4];
                const uint32_t bl0 = Bsl[rb * GLD + kk + t4];
                const uint32_t bl1 = Bsl[rb * GLD + kk + t4 + 4];
                #pragma unroll
                for (int mt = 0; mt < 2; mt++) {
                    mma_bf16(acc[mt][nt], al[mt], bh0, bh1);
                    mma_bf16(acc[mt][nt], ah[mt], bl0, bl1);
                    mma_bf16(acc[mt][nt], ah[mt], bh0, bh1);
                }
            }
        }

        __syncthreads();
        if (i + 2 < ntiles) {
            load_stage(i & 1, (i + 2) * GBK);
            CP_COMMIT();
        }
    }

    // ---------------- epilogue ----------------
    if (outproj) {
        #pragma unroll
        for (int nt = 0; nt < 8; nt++) {
            const int col = bn + wn * 64 + nt * 8 + 2 * t4;
            const float2 bb = *(const float2*)(bias + col);
            #pragma unroll
            for (int mt = 0; mt < 2; mt++) {
                const int row0 = bm + wm * 32 + mt * 16 + gi;
                float2 o0, o1;
                o0.x = acc[mt][nt][0] + bb.x; o0.y = acc[mt][nt][1] + bb.y;
                o1.x = acc[mt][nt][2] + bb.x; o1.y = acc[mt][nt][3] + bb.y;
                *(float2*)(Cout + (size_t)row0 * D_MODEL + col)       = o0;
                *(float2*)(Cout + (size_t)(row0 + 8) * D_MODEL + col) = o1;
            }
        }
    } else if (z < 2) {
        uint32_t* Ho = (z == 0) ? QhO : KhO;
        uint32_t* Lo = (z == 0) ? QlO : KlO;
        #pragma unroll
        for (int nt = 0; nt < 8; nt++) {
            const int col  = bn + wn * 64 + nt * 8 + 2 * t4;
            const int colu = col >> 1;
            const float2 bb = *(const float2*)(bias + col);
            #pragma unroll
            for (int mt = 0; mt < 2; mt++) {
                const int row0 = bm + wm * 32 + mt * 16 + gi;
                uint32_t ph, pl;
                bsplit2(acc[mt][nt][0] + bb.x, acc[mt][nt][1] + bb.y, ph, pl);
                Ho[(size_t)row0 * DU + colu] = ph;
                Lo[(size_t)row0 * DU + colu] = pl;
                bsplit2(acc[mt][nt][2] + bb.x, acc[mt][nt][3] + bb.y, ph, pl);
                Ho[(size_t)(row0 + 8) * DU + colu] = ph;
                Lo[(size_t)(row0 + 8) * DU + colu] = pl;
            }
        }
    } else {
        // V: transposed packed per (b,h): [dh][key-pair]
        #pragma unroll
        for (int nt = 0; nt < 8; nt++) {
            const int cg = bn + wn * 64 + nt * 8 + 2 * t4;
            const float2 bb = *(const float2*)(bias + cg);
            #pragma unroll
            for (int mt = 0; mt < 2; mt++) {
                const int r = bm + wm * 32 + mt * 16 + gi;
                const float c0 = acc[mt][nt][0] + bb.x;
                const float c1 = acc[mt][nt][1] + bb.y;
                const float c2 = acc[mt][nt][2] + bb.x;
                const float c3 = acc[mt][nt][3] + bb.y;
                const float p0 = __shfl_xor_sync(0xffffffffu, c0, 4);
                const float p1 = __shfl_xor_sync(0xffffffffu, c1, 4);
                const float p2 = __shfl_xor_sync(0xffffffffu, c2, 4);
                const float p3 = __shfl_xor_sync(0xffffffffu, c3, 4);
                uint32_t ph, pl;
                if ((gi & 1) == 0) {
                    // column cg, token pairs (r, r+1) and (r+8, r+9)
                    const int bb_ = r >> 10, s = r & 1023;
                    const int h_ = cg >> 6, dh = cg & 63;
                    const size_t plane = ((size_t)(bb_ * NH + h_) * DH + dh) * SU2;
                    bsplit2(c0, p0, ph, pl);
                    VtHO[plane + (s >> 1)] = ph;
                    VtLO[plane + (s >> 1)] = pl;
                    bsplit2(c2, p2, ph, pl);
                    VtHO[plane + (s >> 1) + 4] = ph;
                    VtLO[plane + (s >> 1) + 4] = pl;
                } else {
                    // column cg+1, token pairs (r-1, r) and (r+7, r+8)
                    const int rr = r - 1;
                    const int bb_ = rr >> 10, s = rr & 1023;
                    const int h_ = (cg + 1) >> 6, dh = (cg + 1) & 63;
                    const size_t plane = ((size_t)(bb_ * NH + h_) * DH + dh) * SU2;
                    bsplit2(p1, c1, ph, pl);
                    VtHO[plane + (s >> 1)] = ph;
                    VtLO[plane + (s >> 1)] = pl;
                    bsplit2(p3, c3, ph, pl);
                    VtHO[plane + (s >> 1) + 4] = ph;
                    VtLO[plane + (s >> 1) + 4] = pl;
                }
            }
        }
    }
}

// ---------------------------------------------------------------------------
// Flash attention v4: bf16x3, all operands pre-packed; cp.async 2-stage tiles.
// Grid (S/128, H, B), 256 threads = 8 warps; warp w owns 16 query rows.
// Tiles per stage (u32, row stride 36): Kh, Kl [64 keys][32 dh-pairs];
// Vh, Vl [64 dh][32 key-pairs] (pre-transposed by the V GEMM).
// Fragment read banks (36*row + 8kc + t4) % 32 are conflict-free.
// ---------------------------------------------------------------------------
#define A2_LDK 36
#define A2_TILE (64 * A2_LDK)           // 2304 u32
#define A2_STAGE (4 * A2_TILE)          // 9216 u32
#define A2_PH  (2 * A2_STAGE)           // 18432
#define A2_PL  (A2_PH + 8 * 16 * A2_LDK)
#define A2_MSK (A2_PL + 8 * 16 * A2_LDK)
#define A2_SMEM ((A2_MSK + 32) * 4)     // ~110.8 KB

__global__ void __launch_bounds__(256, 1) attn_bf16_kernel(
    const uint32_t* __restrict__ Qh, const uint32_t* __restrict__ Ql,
    const uint32_t* __restrict__ Kh, const uint32_t* __restrict__ Kl,
    const uint32_t* __restrict__ VtH, const uint32_t* __restrict__ VtL,
    const unsigned char* __restrict__ kpm,
    uint32_t* __restrict__ Oh, uint32_t* __restrict__ Ol)
{
    extern __shared__ uint32_t su[];

    const int b   = blockIdx.z;
    const int h   = blockIdx.y;
    const int qt  = gridDim.x - 1 - blockIdx.x;   // heavy tiles first
    const int tid = threadIdx.x;
    const int w    = tid >> 5;
    const int lane = tid & 31;
    const int gi = lane >> 2;
    const int t4 = lane & 3;

    const int q0   = qt * 128;
    const int row0 = q0 + w * 16 + gi;

    const float scale = 0.125f;
    const float NEG = -1e30f;

    // ---- Q fragments: direct u32 loads from packed slabs ----
    uint32_t qh[4][4], ql[4][4];
    {
        const uint32_t* q0h = Qh + (size_t)(b * S_LEN + row0) * DU + h * 32;
        const uint32_t* q1h = q0h + 8 * DU;
        const uint32_t* q0l = Ql + (size_t)(b * S_LEN + row0) * DU + h * 32;
        const uint32_t* q1l = q0l + 8 * DU;
        #pragma unroll
        for (int kc = 0; kc < 4; kc++) {
            qh[kc][0] = q0h[kc * 8 + t4];
            qh[kc][1] = q1h[kc * 8 + t4];
            qh[kc][2] = q0h[kc * 8 + t4 + 4];
            qh[kc][3] = q1h[kc * 8 + t4 + 4];
            ql[kc][0] = q0l[kc * 8 + t4];
            ql[kc][1] = q1l[kc * 8 + t4];
            ql[kc][2] = q0l[kc * 8 + t4 + 4];
            ql[kc][3] = q1l[kc * 8 + t4 + 4];
        }
    }

    float oc[8][4];
    #pragma unroll
    for (int nt = 0; nt < 8; nt++)
        #pragma unroll
        for (int i = 0; i < 4; i++) oc[nt][i] = 0.0f;
    float m0 = NEG, m1 = NEG, l0 = 0.0f, l1 = 0.0f;

    // tile loader mapping: row = tid>>2 (0..63), seg = tid&3 (8 u32 each)
    const int ldr = tid >> 2;
    const int seg = tid & 3;
    const uint32_t smbase = (uint32_t)__cvta_generic_to_shared(su);
    const uint32_t dsto = (uint32_t)(ldr * A2_LDK + seg * 8) * 4;

    const uint32_t* khg = Kh + (size_t)(b * S_LEN + ldr) * DU + h * 32 + seg * 8;
    const uint32_t* klg = Kl + (size_t)(b * S_LEN + ldr) * DU + h * 32 + seg * 8;
    const uint32_t* vhg = VtH + ((size_t)(b * NH + h) * DH + ldr) * SU2 + seg * 8;
    const uint32_t* vlg = VtL + ((size_t)(b * NH + h) * DH + ldr) * SU2 + seg * 8;
    const size_t kstep = (size_t)DU;   // per key row

    auto load_tile = [&](int st, int kt) {
        const int k0 = kt * 64;
        const uint32_t sb = smbase + (uint32_t)st * (A2_STAGE * 4) + dsto;
        cpa16(sb,                     khg + (size_t)k0 * kstep);
        cpa16(sb + 16,                khg + (size_t)k0 * kstep + 4);
        cpa16(sb + A2_TILE * 4,       klg + (size_t)k0 * kstep);
        cpa16(sb + A2_TILE * 4 + 16,  klg + (size_t)k0 * kstep + 4);
        cpa16(sb + A2_TILE * 8,       vhg + k0 / 2);
        cpa16(sb + A2_TILE * 8 + 16,  vhg + k0 / 2 + 4);
        cpa16(sb + A2_TILE * 12,      vlg + k0 / 2);
        cpa16(sb + A2_TILE * 12 + 16, vlg + k0 / 2 + 4);
        if (tid < 4)
            cpa16(smbase + (A2_MSK + st * 16) * 4 + tid * 16,
                  kpm + (size_t)b * S_LEN + k0 + tid * 16);
    };

    uint32_t* pwh = su + A2_PH + w * 16 * A2_LDK;
    uint32_t* pwl = su + A2_PL + w * 16 * A2_LDK;
    const int ktiles = 2 * qt + 2;

    load_tile(0, 0);
    CP_COMMIT();
    load_tile(1, 1);
    CP_COMMIT();

    for (int kt = 0; kt < ktiles; kt++) {
        const int k0 = kt * 64;
        if (kt + 1 < ktiles) CP_WAIT1(); else CP_WAIT0();
        __syncthreads();

        const uint32_t* St  = su + (kt & 1) * A2_STAGE;
        const uint32_t* Ksh = St;
        const uint32_t* Ksl = St + A2_TILE;
        const uint32_t* Vsh = St + 2 * A2_TILE;
        const uint32_t* Vsl = St + 3 * A2_TILE;
        const unsigned char* mb = (const unsigned char*)(su + A2_MSK + (kt & 1) * 16);

        // ---- S = Q K^T (bf16 x3) ----
        float sc[8][4];
        #pragma unroll
        for (int nt = 0; nt < 8; nt++)
            #pragma unroll
            for (int i = 0; i < 4; i++) sc[nt][i] = 0.0f;

        #pragma unroll
        for (int kc = 0; kc < 4; kc++) {
            uint32_t bh[8][2], bl[8][2];
            #pragma unroll
            for (int nt = 0; nt < 8; nt++) {
                const int kr = (nt * 8 + gi) * A2_LDK + kc * 8 + t4;
                bh[nt][0] = Ksh[kr];
                bh[nt][1] = Ksh[kr + 4];
                bl[nt][0] = Ksl[kr];
                bl[nt][1] = Ksl[kr + 4];
            }
            #pragma unroll
            for (int nt = 0; nt < 8; nt++) mma_bf16(sc[nt], ql[kc], bh[nt][0], bh[nt][1]);
            #pragma unroll
            for (int nt = 0; nt < 8; nt++) mma_bf16(sc[nt], qh[kc], bl[nt][0], bl[nt][1]);
            #pragma unroll
            for (int nt = 0; nt < 8; nt++) mma_bf16(sc[nt], qh[kc], bh[nt][0], bh[nt][1]);
        }

        // ---- scale + masks + online softmax ----
        const bool needc = (k0 + 63) > row0;
        float rm0 = NEG, rm1 = NEG;
        #pragma unroll
        for (int nt = 0; nt < 8; nt++) {
            const int col = k0 + nt * 8 + 2 * t4;
            const float mg0 = mb[nt * 8 + 2 * t4]     ? NEG : 0.0f;
            const float mg1 = mb[nt * 8 + 2 * t4 + 1] ? NEG : 0.0f;
            float v0 = sc[nt][0] * scale + mg0;
            float v1 = sc[nt][1] * scale + mg1;
            float v2 = sc[nt][2] * scale + mg0;
            float v3 = sc[nt][3] * scale + mg1;
            if (needc) {
                if (col     > row0)     v0 = NEG;
                if (col + 1 > row0)     v1 = NEG;
                if (col     > row0 + 8) v2 = NEG;
                if (col + 1 > row0 + 8) v3 = NEG;
            }
            sc[nt][0] = v0; sc[nt][1] = v1; sc[nt][2] = v2; sc[nt][3] = v3;
            rm0 = fmaxf(rm0, fmaxf(v0, v1));
            rm1 = fmaxf(rm1, fmaxf(v2, v3));
        }
        rm0 = fmaxf(rm0, __shfl_xor_sync(0xffffffffu, rm0, 1, 4));
        rm0 = fmaxf(rm0, __shfl_xor_sync(0xffffffffu, rm0, 2, 4));
        rm1 = fmaxf(rm1, __shfl_xor_sync(0xffffffffu, rm1, 1, 4));
        rm1 = fmaxf(rm1, __shfl_xor_sync(0xffffffffu, rm1, 2, 4));

        const float mn0 = fmaxf(m0, rm0);
        const float mn1 = fmaxf(m1, rm1);
        const float cr0 = __expf(m0 - mn0);
        const float cr1 = __expf(m1 - mn1);

        float ps0 = 0.0f, ps1 = 0.0f;
        #pragma unroll
        for (int nt = 0; nt < 8; nt++) {
            const float e0 = __expf(sc[nt][0] - mn0);
            const float e1 = __expf(sc[nt][1] - mn0);
            const float e2 = __expf(sc[nt][2] - mn1);
            const float e3 = __expf(sc[nt][3] - mn1);
            sc[nt][0] = e0; sc[nt][1] = e1; sc[nt][2] = e2; sc[nt][3] = e3;
            ps0 += e0 + e1;
            ps1 += e2 + e3;
        }
        ps0 += __shfl_xor_sync(0xffffffffu, ps0, 1, 4);
        ps0 += __shfl_xor_sync(0xffffffffu, ps0, 2, 4);
        ps1 += __shfl_xor_sync(0xffffffffu, ps1, 1, 4);
        ps1 += __shfl_xor_sync(0xffffffffu, ps1, 2, 4);

        l0 = l0 * cr0 + ps0;  m0 = mn0;
        l1 = l1 * cr1 + ps1;  m1 = mn1;

        #pragma unroll
        for (int nt = 0; nt < 8; nt++) {
            oc[nt][0] *= cr0; oc[nt][1] *= cr0;
            oc[nt][2] *= cr1; oc[nt][3] *= cr1;
        }

        // ---- P -> per-warp smem, packed bf16x2 hi/lo ----
        __syncwarp();
        #pragma unroll
        for (int nt = 0; nt < 8; nt++) {
            uint32_t ph, pl;
            bsplit2(sc[nt][0], sc[nt][1], ph, pl);
            pwh[gi * A2_LDK + nt * 4 + t4] = ph;
            pwl[gi * A2_LDK + nt * 4 + t4] = pl;
            bsplit2(sc[nt][2], sc[nt][3], ph, pl);
            pwh[(gi + 8) * A2_LDK + nt * 4 + t4] = ph;
            pwl[(gi + 8) * A2_LDK + nt * 4 + t4] = pl;
        }
        __syncwarp();

        // ---- O += P V (bf16 x3) ----
        #pragma unroll
        for (int kc = 0; kc < 4; kc++) {
            uint32_t ah[4], al[4];
            ah[0] = pwh[gi * A2_LDK + kc * 8 + t4];
            al[0] = pwl[gi * A2_LDK + kc * 8 + t4];
            ah[1] = pwh[(gi + 8) * A2_LDK + kc * 8 + t4];
            al[1] = pwl[(gi + 8) * A2_LDK + kc * 8 + t4];
            ah[2] = pwh[gi * A2_LDK + kc * 8 + t4 + 4];
            al[2] = pwl[gi * A2_LDK + kc * 8 + t4 + 4];
            ah[3] = pwh[(gi + 8) * A2_LDK + kc * 8 + t4 + 4];
            al[3] = pwl[(gi + 8) * A2_LDK + kc * 8 + t4 + 4];

            uint32_t bh[8][2], bl[8][2];
            #pragma unroll
            for (int nt = 0; nt < 8; nt++) {
                const int vr = (nt * 8 + gi) * A2_LDK + kc * 8 + t4;
                bh[nt][0] = Vsh[vr];
                bh[nt][1] = Vsh[vr + 4];
                bl[nt][0] = Vsl[vr];
                bl[nt][1] = Vsl[vr + 4];
            }
            #pragma unroll
            for (int nt = 0; nt < 8; nt++) mma_bf16(oc[nt], al, bh[nt][0], bh[nt][1]);
            #pragma unroll
            for (int nt = 0; nt < 8; nt++) mma_bf16(oc[nt], ah, bl[nt][0], bl[nt][1]);
            #pragma unroll
            for (int nt = 0; nt < 8; nt++) mma_bf16(oc[nt], ah, bh[nt][0], bh[nt][1]);
        }

        __syncthreads();
        if (kt + 2 < ktiles) {
            load_tile(kt & 1, kt + 2);
            CP_COMMIT();
        }
    }

    // ---- normalize + store packed hi/lo ----
    const float inv0 = 1.0f / l0;
    const float inv1 = 1.0f / l1;
    uint32_t* o0h = Oh + (size_t)(b * S_LEN + row0) * DU + h * 32;
    uint32_t* o0l = Ol + (size_t)(b * S_LEN + row0) * DU + h * 32;
    uint32_t* o1h = o0h + 8 * DU;
    uint32_t* o1l = o0l + 8 * DU;
    #pragma unroll
    for (int nt = 0; nt < 8; nt++) {
        uint32_t ph, pl;
        bsplit2(oc[nt][0] * inv0, oc[nt][1] * inv0, ph, pl);
        o0h[nt * 4 + t4] = ph;
        o0l[nt * 4 + t4] = pl;
        bsplit2(oc[nt][2] * inv1, oc[nt][3] * inv1, ph, pl);
        o1h[nt * 4 + t4] = ph;
        o1l[nt * 4 + t4] = pl;
    }
}

// ---------------------------------------------------------------------------
// Launch
// ---------------------------------------------------------------------------
extern "C" void kernel_launch(void* const* d_in, const int* in_sizes, int n_in,
                              void* d_out, int out_size)
{
    const float* q    = (const float*)d_in[0];
    const float* k    = (const float*)d_in[1];
    const float* v    = (const float*)d_in[2];
    const unsigned char* kpm = (const unsigned char*)d_in[3];
    const float* Wq = (const float*)d_in[4];
    const float* bq = (const float*)d_in[5];
    const float* Wk = (const float*)d_in[6];
    const float* bk = (const float*)d_in[7];
    const float* Wv = (const float*)d_in[8];
    const float* bv = (const float*)d_in[9];
    const float* Wo = (const float*)d_in[10];
    const float* bo = (const float*)d_in[11];
    float* out = (float*)d_out;

    void *pAh, *pAl, *pWh, *pWl, *pQh, *pQl, *pKh, *pKl, *pVh, *pVl, *pOh, *pOl;
    cudaGetSymbolAddress(&pAh, g_Ahp);
    cudaGetSymbolAddress(&pAl, g_Alp);
    cudaGetSymbolAddress(&pWh, g_Whp);
    cudaGetSymbolAddress(&pWl, g_Wlp);
    cudaGetSymbolAddress(&pQh, g_Qh);
    cudaGetSymbolAddress(&pQl, g_Ql);
    cudaGetSymbolAddress(&pKh, g_Kh);
    cudaGetSymbolAddress(&pKl, g_Kl);
    cudaGetSymbolAddress(&pVh, g_VtH);
    cudaGetSymbolAddress(&pVl, g_VtL);
    cudaGetSymbolAddress(&pOh, g_Oh);
    cudaGetSymbolAddress(&pOl, g_Ol);

    cudaFuncSetAttribute(attn_bf16_kernel,
                         cudaFuncAttributeMaxDynamicSharedMemorySize, A2_SMEM);
    cudaFuncSetAttribute(gemm5_bf16,
                         cudaFuncAttributeMaxDynamicSharedMemorySize, G4_SMEM);

    // 1) pre-split weights + raw q/k/v activations
    dim3 wgrid(DD / 1024, 4);
    split_weights_kernel<<<wgrid, 256>>>(Wq, Wk, Wv, Wo,
                                         (uint32_t*)pWh, (uint32_t*)pWl);
    dim3 sgrid((M_ROWS * D_MODEL) / 1024, 3);
    split_acts_kernel<<<sgrid, 256>>>(q, k, v,
                                      (uint32_t*)pAh, (uint32_t*)pAl);

    // 2) fused Q/K/V projections -> packed (V transposed)
    dim3 ggrid(D_MODEL / 128, M_ROWS / 128, 3);
    gemm5_bf16<<<ggrid, 256, G4_SMEM>>>(
        (const uint32_t*)pAh, (const uint32_t*)pAl,
        (const uint32_t*)pWh, (const uint32_t*)pWl,
        bq, bk, bv,
        (uint32_t*)pQh, (uint32_t*)pQl,
        (uint32_t*)pKh, (uint32_t*)pKl,
        (uint32_t*)pVh, (uint32_t*)pVl,
        nullptr, 0, 0);

    // 3) attention -> packed Ao
    dim3 agrid(S_LEN / 128, NH, BATCH);
    attn_bf16_kernel<<<agrid, 256, A2_SMEM>>>(
        (const uint32_t*)pQh, (const uint32_t*)pQl,
        (const uint32_t*)pKh, (const uint32_t*)pKl,
        (const uint32_t*)pVh, (const uint32_t*)pVl,
        kpm,
        (uint32_t*)pOh, (uint32_t*)pOl);

    // 4) output projection (weight slab 3) -> fp32 out
    dim3 ogrid(D_MODEL / 128, M_ROWS / 128, 1);
    gemm5_bf16<<<ogrid, 256, G4_SMEM>>>(
        (const uint32_t*)pOh, (const uint32_t*)pOl,
        (const uint32_t*)pWh, (const uint32_t*)pWl,
        bo, bo, bo,
        nullptr, nullptr, nullptr, nullptr, nullptr, nullptr,
        out, 3, 1);
}